// round 10
// baseline (speedup 1.0000x reference)
#include <cuda_runtime.h>
#include <cstdint>

#define Bn 32
#define Fn 64
#define Ln 8192
#define Pn 96
#define SR 132    // data tile row stride (floats)

typedef unsigned long long ull;

// ---------------- scratch (device globals) ----------------
__device__ float g_mean[Bn * Fn];
__device__ float g_istd[Bn * Fn];
__device__ float g_stdp[Bn * Fn];
__device__ float g_KV[Bn * 512];
__device__ float g_Z[Bn * 64];
__device__ float g_M[Bn * Pn * Fn];
// pre-folded, DUPLICATED (f32x2) weights: layout [k(=input dim)][e(=output dim)]
__device__ float2 g_Wqp[4096], g_Wkp[4096], g_Wvp[4096], g_Wop[4096];
__device__ float g_dq[64], g_cq[64], g_dk[64], g_ck[64], g_dv[64], g_cv[64];

// ---------------- helpers ----------------
__device__ __forceinline__ void fma2(ull& d, ull a, ull b) {
    asm("fma.rn.f32x2 %0, %1, %2, %0;" : "+l"(d) : "l"(a), "l"(b));
}
__device__ __forceinline__ float2 upk(ull v) {
    float2 r;
    asm("mov.b64 {%0, %1}, %2;" : "=f"(r.x), "=f"(r.y) : "l"(v));
    return r;
}
__device__ __forceinline__ ull pk2(float a, float b) {
    ull r;
    asm("mov.b64 %0, {%1, %2};" : "=l"(r) : "f"(a), "f"(b));
    return r;
}
__device__ __forceinline__ float phi_fn(float v) {
    return v > 0.f ? v + 1.f : __expf(v);   // elu(x)+1
}

// ---------------- prep (block 0) + zero accumulators (blocks 1..32) ----------------
__global__ void __launch_bounds__(256) k_prep(
    const float* __restrict__ lnw, const float* __restrict__ lnb,
    const float* __restrict__ Wq, const float* __restrict__ bq,
    const float* __restrict__ Wk, const float* __restrict__ bk,
    const float* __restrict__ Wv, const float* __restrict__ bv,
    const float* __restrict__ Wo)
{
    if (blockIdx.x > 0) {
        int zb = blockIdx.x - 1;
        int base = zb * 6144;
        for (int i = threadIdx.x; i < 6144; i += 256) g_M[base + i] = 0.f;
        if (zb < 16) {
            for (int i = threadIdx.x; i < 1024; i += 256) g_KV[zb * 1024 + i] = 0.f;
        } else {
            int zz = zb - 16;
            for (int i = threadIdx.x; i < 128; i += 256) g_Z[zz * 128 + i] = 0.f;
        }
        return;
    }
    int tid = threadIdx.x;
#pragma unroll
    for (int i = 0; i < 16; i++) {
        int idx = tid + i * 256;          // idx = f*64 + e
        int f = idx >> 6, e = idx & 63;
        float lw = lnw[f];
        float wq = Wq[e * 64 + f] * lw;  g_Wqp[idx] = make_float2(wq, wq);
        float wk = Wk[e * 64 + f] * lw;  g_Wkp[idx] = make_float2(wk, wk);
        float wv = Wv[e * 64 + f] * lw;  g_Wvp[idx] = make_float2(wv, wv);
        float wo = Wo[e * 64 + f];       g_Wop[idx] = make_float2(wo, wo);  // WoT[k=e_att][fo]
    }
    if (tid < 64) {
        int e = tid;
        float dq = 0.f, cq = 0.f, dk = 0.f, ck = 0.f, dv = 0.f, cv = 0.f;
        for (int f = 0; f < 64; f++) {
            float lw = lnw[f], lb2 = lnb[f];
            float wq = Wq[e * 64 + f], wk = Wk[e * 64 + f], wv = Wv[e * 64 + f];
            dq += wq * lw;  cq = fmaf(lb2, wq, cq);
            dk += wk * lw;  ck = fmaf(lb2, wk, ck);
            dv += wv * lw;  cv = fmaf(lb2, wv, cv);
        }
        g_dq[e] = dq; g_cq[e] = cq + bq[e];
        g_dk[e] = dk; g_ck[e] = ck + bk[e];
        g_dv[e] = dv; g_cv[e] = cv + bv[e];
    }
}

// ---------------- RevIN stats per (b,f) ----------------
__global__ void __launch_bounds__(256) k_stats(const float* __restrict__ x) {
    int bf = blockIdx.x;
    const float4* p = (const float4*)(x + (size_t)bf * Ln);
    float s1 = 0.f, s2 = 0.f;
    for (int i = threadIdx.x; i < Ln / 4; i += 256) {
        float4 v = p[i];
        s1 += (v.x + v.y) + (v.z + v.w);
        s2 = fmaf(v.x, v.x, s2); s2 = fmaf(v.y, v.y, s2);
        s2 = fmaf(v.z, v.z, s2); s2 = fmaf(v.w, v.w, s2);
    }
    __shared__ float r1[256], r2[256];
    r1[threadIdx.x] = s1; r2[threadIdx.x] = s2;
    __syncthreads();
    for (int s = 128; s > 0; s >>= 1) {
        if (threadIdx.x < s) {
            r1[threadIdx.x] += r1[threadIdx.x + s];
            r2[threadIdx.x] += r2[threadIdx.x + s];
        }
        __syncthreads();
    }
    if (threadIdx.x == 0) {
        float S1 = r1[0], S2 = r2[0];
        float mean = S1 / (float)Ln;
        float var = (S2 - S1 * mean) / (float)(Ln - 1);
        var = fmaxf(var, 0.f);
        float stdp = sqrtf(var) + 1e-5f;
        g_mean[bf] = mean; g_stdp[bf] = stdp; g_istd[bf] = 1.f / stdp;
    }
}

// 64-deep GEMM micro-tile, dup weights: 4 outputs (e0..e0+3) x 2 l-pairs.
// hp = xns + 2*pg ; wd = dup weight ull base. 12 inst per 8 FMA2, 0 MOVs.
__device__ __forceinline__ void gemm4x2(const float* __restrict__ hp,
                                        const ull* __restrict__ wd, int e0,
                                        ull a[4][2]) {
#pragma unroll
    for (int i = 0; i < 4; i++) { a[i][0] = a[i][1] = 0ULL; }
#pragma unroll 8
    for (int k = 0; k < 64; k++) {
        ull h0 = *(const ull*)(hp + k * SR);
        ull h1 = *(const ull*)(hp + k * SR + 64);
        ulonglong2 wA = *(const ulonglong2*)(wd + k * 64 + e0);
        ulonglong2 wB = *(const ulonglong2*)(wd + k * 64 + e0 + 2);
        fma2(a[0][0], wA.x, h0); fma2(a[0][1], wA.x, h1);
        fma2(a[1][0], wA.y, h0); fma2(a[1][1], wA.y, h1);
        fma2(a[2][0], wB.x, h0); fma2(a[2][1], wB.x, h1);
        fma2(a[3][0], wB.y, h0); fma2(a[3][1], wB.y, h1);
    }
}

// ---------------- kernel 2: K/V projections + KV,Z (512 threads) ----------------
__global__ void __launch_bounds__(512, 2) k_kv(
    const float* __restrict__ x, const float* __restrict__ gamma, const float* __restrict__ beta)
{
    extern __shared__ float sm[];
    float* xns = sm;                     // 64*SR; later phi(K)
    float* vb  = sm + 64 * SR;           // 64*SR
    ull*   wd  = (ull*)(sm + 2 * 64 * SR);  // 4096 ulls = 32768 B
    __shared__ float mus[128], rss[128], As[64], Cs[64];
    __shared__ float dks[64], cks[64], dvs[64], cvs[64];

    int b = blockIdx.y, tid = threadIdx.x;
    int l0b = blockIdx.x * 128;

    if (tid < 64) {
        float a = gamma[tid] * g_istd[b * 64 + tid];
        As[tid] = a;
        Cs[tid] = beta[tid] - g_mean[b * 64 + tid] * a;
        dks[tid] = g_dk[tid]; cks[tid] = g_ck[tid];
        dvs[tid] = g_dv[tid]; cvs[tid] = g_cv[tid];
    }
#pragma unroll
    for (int i = 0; i < 4; i++)   // wd <- Wv dup (2048 float4)
        ((float4*)wd)[tid + i * 512] = ((const float4*)g_Wvp)[tid + i * 512];
    __syncthreads();
#pragma unroll
    for (int i = 0; i < 4; i++) {
        int idx = tid + i * 512;
        int f = idx >> 5, c = idx & 31;
        float4 v = *(const float4*)(x + ((size_t)(b * 64 + f)) * Ln + l0b + c * 4);
        float a = As[f], c0 = Cs[f];
        v.x = fmaf(v.x, a, c0); v.y = fmaf(v.y, a, c0);
        v.z = fmaf(v.z, a, c0); v.w = fmaf(v.w, a, c0);
        *(float4*)(xns + f * SR + c * 4) = v;
    }
    __syncthreads();
    if (tid < 128) {
        float s1 = 0.f, s2 = 0.f;
#pragma unroll
        for (int f = 0; f < 64; f++) { float t = xns[f * SR + tid]; s1 += t; s2 = fmaf(t, t, s2); }
        float mu = s1 * (1.f / 64.f);
        mus[tid] = mu;
        rss[tid] = rsqrtf(fmaf(-mu, mu, s2 * (1.f / 64.f)) + 1e-5f);
    }
    __syncthreads();

    int pg = (tid & 15) + 16 * (tid >> 8);   // 0..31
    int eg = (tid >> 4) & 15;
    int e0 = eg * 4;
    const float* hp = xns + 2 * pg;

    float2 mu0 = upk(*(const ull*)(mus + 2 * pg));
    float2 mu1 = upk(*(const ull*)(mus + 2 * pg + 64));
    float2 rs0 = upk(*(const ull*)(rss + 2 * pg));
    float2 rs1 = upk(*(const ull*)(rss + 2 * pg + 64));

    ull a[4][2];

    // ---- V GEMM -> vb ----
    gemm4x2(hp, wd, e0, a);
#pragma unroll
    for (int i = 0; i < 4; i++) {
        int e = e0 + i; float dv = dvs[e], cv = cvs[e];
        float2 s0 = upk(a[i][0]), s1 = upk(a[i][1]);
        *(ull*)(vb + e * SR + 2 * pg) =
            pk2(fmaf(rs0.x, s0.x - mu0.x * dv, cv), fmaf(rs0.y, s0.y - mu0.y * dv, cv));
        *(ull*)(vb + e * SR + 2 * pg + 64) =
            pk2(fmaf(rs1.x, s1.x - mu1.x * dv, cv), fmaf(rs1.y, s1.y - mu1.y * dv, cv));
    }
    __syncthreads();   // V GEMM reads of wd done
#pragma unroll
    for (int i = 0; i < 4; i++)   // wd <- Wk dup
        ((float4*)wd)[tid + i * 512] = ((const float4*)g_Wkp)[tid + i * 512];
    __syncthreads();

    // ---- K GEMM -> phi ----
    gemm4x2(hp, wd, e0, a);
    ull kw[4][2];
#pragma unroll
    for (int i = 0; i < 4; i++) {
        int e = e0 + i; float dk = dks[e], ck = cks[e];
        float2 s0 = upk(a[i][0]), s1 = upk(a[i][1]);
        kw[i][0] = pk2(phi_fn(fmaf(rs0.x, s0.x - mu0.x * dk, ck)),
                       phi_fn(fmaf(rs0.y, s0.y - mu0.y * dk, ck)));
        kw[i][1] = pk2(phi_fn(fmaf(rs1.x, s1.x - mu1.x * dk, ck)),
                       phi_fn(fmaf(rs1.y, s1.y - mu1.y * dk, ck)));
    }
    __syncthreads();   // all GEMM reads of xns done
#pragma unroll
    for (int i = 0; i < 4; i++) {
        *(ull*)(xns + (e0 + i) * SR + 2 * pg)      = kw[i][0];
        *(ull*)(xns + (e0 + i) * SR + 2 * pg + 64) = kw[i][1];
    }
    __syncthreads();

    // ---- KV accumulation: one (hh,d,e) per thread ----
    {
        int hh = tid >> 6;
        int d  = (tid >> 3) & 7;
        int e2 = tid & 7;
        const float* kr = xns + (hh * 8 + d) * SR;
        const float* vr = vb + (hh * 8 + e2) * SR;
        ull acc = 0ULL;
#pragma unroll 8
        for (int j = 0; j < 128; j += 4) {
            ulonglong2 kk = *(const ulonglong2*)(kr + j);
            ulonglong2 vv = *(const ulonglong2*)(vr + j);
            fma2(acc, kk.x, vv.x);
            fma2(acc, kk.y, vv.y);
        }
        float2 t = upk(acc);
        atomicAdd(&g_KV[(b * 8 + hh) * 64 + d * 8 + e2], t.x + t.y);
    }
    if (tid < 64) {
        const float* kr = xns + tid * SR;
        float s = 0.f;
#pragma unroll
        for (int j = 0; j < 128; j += 4) {
            float4 v = *(const float4*)(kr + j);
            s += (v.x + v.y) + (v.z + v.w);
        }
        atomicAdd(&g_Z[b * 64 + tid], s);
    }
}

// ---------------- kernel 3: Q, attention, Wo+residual, fused temporal (512 threads) ----------------
__global__ void __launch_bounds__(512, 2) k_qo(
    const float* __restrict__ x, const float* __restrict__ gamma, const float* __restrict__ beta,
    const float* __restrict__ bo, const float* __restrict__ Wlin)
{
    extern __shared__ float sm[];
    ull*   wd  = (ull*)sm;               // 4096 ulls (Wq dup, then WoT dup)
    float* xns = sm + 8192;              // 64*SR
    float* qb  = sm + 8192 + 64 * SR;    // 64*SR; later y tile (66-ull row stride)
    ull*   wy  = (ull*)qb;               // y: 64 x 66 ulls = 33792 B (= region size)
    ull*   wlu = (ull*)sm;               // Wlin slab: 96 x 64 ulls = 49152 B over wd+xns (66560 B)
    __shared__ float mus[128], rss[128], As[64], Cs[64], dqs[64], cqs[64], bos[64];
    __shared__ float KVs[512], Zs[64];

    int b = blockIdx.y, tid = threadIdx.x;
    int l0b = blockIdx.x * 128;

    if (tid < 64) {
        float a = gamma[tid] * g_istd[b * 64 + tid];
        As[tid] = a;
        Cs[tid] = beta[tid] - g_mean[b * 64 + tid] * a;
        dqs[tid] = g_dq[tid]; cqs[tid] = g_cq[tid];
        bos[tid] = bo[tid];
        Zs[tid] = g_Z[b * 64 + tid];
    }
    KVs[tid] = g_KV[b * 512 + tid];
#pragma unroll
    for (int i = 0; i < 4; i++)   // wd <- Wq dup
        ((float4*)wd)[tid + i * 512] = ((const float4*)g_Wqp)[tid + i * 512];
    __syncthreads();
#pragma unroll
    for (int i = 0; i < 4; i++) {
        int idx = tid + i * 512;
        int f = idx >> 5, c = idx & 31;
        float4 v = *(const float4*)(x + ((size_t)(b * 64 + f)) * Ln + l0b + c * 4);
        float a = As[f], c0 = Cs[f];
        v.x = fmaf(v.x, a, c0); v.y = fmaf(v.y, a, c0);
        v.z = fmaf(v.z, a, c0); v.w = fmaf(v.w, a, c0);
        *(float4*)(xns + f * SR + c * 4) = v;
    }
    __syncthreads();
    if (tid < 128) {
        float s1 = 0.f, s2 = 0.f;
#pragma unroll
        for (int f = 0; f < 64; f++) { float t = xns[f * SR + tid]; s1 += t; s2 = fmaf(t, t, s2); }
        float mu = s1 * (1.f / 64.f);
        mus[tid] = mu;
        rss[tid] = rsqrtf(fmaf(-mu, mu, s2 * (1.f / 64.f)) + 1e-5f);
    }
    __syncthreads();

    int pg = (tid & 15) + 16 * (tid >> 8);
    int eg = (tid >> 4) & 15;
    int e0 = eg * 4;

    float2 mu0 = upk(*(const ull*)(mus + 2 * pg));
    float2 mu1 = upk(*(const ull*)(mus + 2 * pg + 64));
    float2 rs0 = upk(*(const ull*)(rss + 2 * pg));
    float2 rs1 = upk(*(const ull*)(rss + 2 * pg + 64));

    ull a[4][2];

    // ---- Q GEMM -> phi -> qb ----
    gemm4x2(xns + 2 * pg, wd, e0, a);
#pragma unroll
    for (int i = 0; i < 4; i++) {
        int e = e0 + i; float dq = dqs[e], cq = cqs[e];
        float2 s0 = upk(a[i][0]), s1 = upk(a[i][1]);
        *(ull*)(qb + e * SR + 2 * pg) =
            pk2(phi_fn(fmaf(rs0.x, s0.x - mu0.x * dq, cq)),
                phi_fn(fmaf(rs0.y, s0.y - mu0.y * dq, cq)));
        *(ull*)(qb + e * SR + 2 * pg + 64) =
            pk2(phi_fn(fmaf(rs1.x, s1.x - mu1.x * dq, cq)),
                phi_fn(fmaf(rs1.y, s1.y - mu1.y * dq, cq)));
    }
    __syncthreads();   // q complete; Wq reads of wd done

    // ---- reload wd <- WoT dup; attention (2 heads/thread, own cells) ----
#pragma unroll
    for (int i = 0; i < 4; i++)
        ((float4*)wd)[tid + i * 512] = ((const float4*)g_Wop)[tid + i * 512];
    {
        int la = tid & 127;
        int hgrp = tid >> 7;   // 0..3
#pragma unroll
        for (int t = 0; t < 2; t++) {
            int hh = hgrp * 2 + t;
            float q[8];
#pragma unroll
            for (int d = 0; d < 8; d++) q[d] = qb[(hh * 8 + d) * SR + la];
            float nrm = 1e-6f;
#pragma unroll
            for (int d = 0; d < 8; d++) nrm = fmaf(q[d], Zs[hh * 8 + d], nrm);
            float inv = 1.f / nrm;
#pragma unroll
            for (int j = 0; j < 8; j++) {
                float s = 0.f;
#pragma unroll
                for (int d = 0; d < 8; d++) s = fmaf(q[d], KVs[hh * 64 + d * 8 + j], s);
                qb[(hh * 8 + j) * SR + la] = s * inv;
            }
        }
    }
    __syncthreads();

    // ---- Wo GEMM + bias + residual -> y (66-ull stride over qb region) ----
    gemm4x2(qb + 2 * pg, wd, e0, a);
    ull yo[4][2];
#pragma unroll
    for (int i = 0; i < 4; i++) {
        int fo = e0 + i;
        float bb = bos[fo];
        float2 r0 = upk(*(const ull*)(xns + fo * SR + 2 * pg));
        float2 r1 = upk(*(const ull*)(xns + fo * SR + 2 * pg + 64));
        float2 s0 = upk(a[i][0]), s1 = upk(a[i][1]);
        yo[i][0] = pk2(s0.x + bb + r0.x, s0.y + bb + r0.y);
        yo[i][1] = pk2(s1.x + bb + r1.x, s1.y + bb + r1.y);
    }
    __syncthreads();   // Wo GEMM qb-reads + residual xns-reads done
#pragma unroll
    for (int i = 0; i < 4; i++) {
        wy[(e0 + i) * 66 + pg]      = yo[i][0];
        wy[(e0 + i) * 66 + pg + 32] = yo[i][1];
    }
    // ---- Wlin slab (96 x 64 ulls, contiguous) over wd+xns region ----
#pragma unroll
    for (int i = 0; i < 6; i++) {
        int idx = tid + i * 512;               // 3072 float4 = 96 rows x 32
        int p = idx >> 5, c4 = idx & 31;
        ((float4*)wlu)[(p << 5) + c4] = *(const float4*)(Wlin + (size_t)p * Ln + l0b + c4 * 4);
    }
    __syncthreads();

    // ---- temporal GEMM: M[b,p,f] += sum_l Wlin[p,l] * y[f,l] ----
    int fg = tid & 15, pg2 = tid >> 4;          // 16 f-groups x 32 p-groups
    ull acc2[3][4];
#pragma unroll
    for (int i = 0; i < 3; i++)
#pragma unroll
        for (int k = 0; k < 4; k++) acc2[i][k] = 0ULL;
#pragma unroll 4
    for (int j = 0; j < 64; j += 2) {
        ulonglong2 yvv[4], wvv[3];
#pragma unroll
        for (int k = 0; k < 4; k++) yvv[k] = *(const ulonglong2*)(wy + (fg + 16 * k) * 66 + j);
#pragma unroll
        for (int i = 0; i < 3; i++) wvv[i] = *(const ulonglong2*)(wlu + (pg2 + 32 * i) * 64 + j);
#pragma unroll
        for (int i = 0; i < 3; i++)
#pragma unroll
            for (int k = 0; k < 4; k++) {
                fma2(acc2[i][k], wvv[i].x, yvv[k].x);
                fma2(acc2[i][k], wvv[i].y, yvv[k].y);
            }
    }
#pragma unroll
    for (int i = 0; i < 3; i++)
#pragma unroll
        for (int k = 0; k < 4; k++) {
            float2 t = upk(acc2[i][k]);
            atomicAdd(&g_M[(b * 96 + pg2 + 32 * i) * 64 + fg + 16 * k], t.x + t.y);
        }
}

// ---------------- kernel 5: denorm + projector ----------------
__global__ void k_epi(const float* __restrict__ gamma, const float* __restrict__ beta,
                      const float* __restrict__ blin, const float* __restrict__ Wp,
                      const float* __restrict__ bp, float* __restrict__ out) {
    int b = blockIdx.x, p = threadIdx.x;
    float bl = blin[p];
    float s = bp[0];
#pragma unroll
    for (int f = 0; f < 64; f++) {
        float y = g_M[(b * 96 + p) * 64 + f] + bl;
        y = (y - beta[f]) / gamma[f];
        y = fmaf(y, g_stdp[b * 64 + f], g_mean[b * 64 + f]);
        s = fmaf(y, Wp[f], s);
    }
    out[b * 96 + p] = s;
}

// ---------------- launch ----------------
extern "C" void kernel_launch(void* const* d_in, const int* in_sizes, int n_in,
                              void* d_out, int out_size) {
    (void)in_sizes; (void)n_in; (void)out_size;
    const float* x     = (const float*)d_in[0];
    const float* gamma = (const float*)d_in[1];
    const float* beta  = (const float*)d_in[2];
    const float* lnw   = (const float*)d_in[3];
    const float* lnb   = (const float*)d_in[4];
    const float* Wq    = (const float*)d_in[5];
    const float* bq    = (const float*)d_in[6];
    const float* Wk    = (const float*)d_in[7];
    const float* bk    = (const float*)d_in[8];
    const float* Wv    = (const float*)d_in[9];
    const float* bv    = (const float*)d_in[10];
    const float* Wo    = (const float*)d_in[11];
    const float* bo    = (const float*)d_in[12];
    const float* Wlin  = (const float*)d_in[13];
    const float* blin  = (const float*)d_in[14];
    const float* Wp    = (const float*)d_in[15];
    const float* bp    = (const float*)d_in[16];
    float* out = (float*)d_out;

    const int SMB = (2 * 64 * SR + 8192) * 4;   // 100352 B for both kernels
    cudaFuncSetAttribute(k_kv, cudaFuncAttributeMaxDynamicSharedMemorySize, SMB);
    cudaFuncSetAttribute(k_qo, cudaFuncAttributeMaxDynamicSharedMemorySize, SMB);

    k_prep<<<33, 256>>>(lnw, lnb, Wq, bq, Wk, bk, Wv, bv, Wo);
    k_stats<<<Bn * Fn, 256>>>(x);
    k_kv<<<dim3(Ln / 128, Bn), 512, SMB>>>(x, gamma, beta);
    k_qo<<<dim3(Ln / 128, Bn), 512, SMB>>>(x, gamma, beta, bo, Wlin);
    k_epi<<<Bn, Pn>>>(gamma, beta, blin, Wp, bp, out);
}

// round 11
// speedup vs baseline: 1.2238x; 1.2238x over previous
#include <cuda_runtime.h>
#include <cstdint>

#define Bn 32
#define Fn 64
#define Ln 8192
#define Pn 96
#define SR 132    // data tile row stride (floats)

typedef unsigned long long ull;

// ---------------- scratch (device globals) ----------------
__device__ float g_mean[Bn * Fn];
__device__ float g_istd[Bn * Fn];
__device__ float g_stdp[Bn * Fn];
__device__ float g_KV[Bn * 512];
__device__ float g_Z[Bn * 64];
__device__ float g_M[Bn * Pn * Fn];
// pre-folded plain-float weights, layout [k(=input dim)][e(=output dim)]
__device__ float g_Wqf[4096], g_Wkf[4096], g_Wvf[4096], g_Wof[4096];
__device__ float g_dq[64], g_cq[64], g_dk[64], g_ck[64], g_dv[64], g_cv[64];

// ---------------- helpers ----------------
__device__ __forceinline__ void fma2(ull& d, ull a, ull b) {
    asm("fma.rn.f32x2 %0, %1, %2, %0;" : "+l"(d) : "l"(a), "l"(b));
}
__device__ __forceinline__ float2 upk(ull v) {
    float2 r;
    asm("mov.b64 {%0, %1}, %2;" : "=f"(r.x), "=f"(r.y) : "l"(v));
    return r;
}
__device__ __forceinline__ ull pk2(float a, float b) {
    ull r;
    asm("mov.b64 %0, {%1, %2};" : "=l"(r) : "f"(a), "f"(b));
    return r;
}
__device__ __forceinline__ ull dup(float a) { return pk2(a, a); }
__device__ __forceinline__ float phi_fn(float v) {
    return v > 0.f ? v + 1.f : __expf(v);   // elu(x)+1
}

// ---------------- prep (block 0) + zero accumulators (blocks 1..32) ----------------
__global__ void __launch_bounds__(256) k_prep(
    const float* __restrict__ lnw, const float* __restrict__ lnb,
    const float* __restrict__ Wq, const float* __restrict__ bq,
    const float* __restrict__ Wk, const float* __restrict__ bk,
    const float* __restrict__ Wv, const float* __restrict__ bv,
    const float* __restrict__ Wo)
{
    if (blockIdx.x > 0) {
        int zb = blockIdx.x - 1;                 // 0..31
        int base = zb * 6144;                    // 32*6144 = Bn*Pn*Fn
        for (int i = threadIdx.x; i < 6144; i += 256) g_M[base + i] = 0.f;
        if (zb < 16) {
            for (int i = threadIdx.x; i < 1024; i += 256) g_KV[zb * 1024 + i] = 0.f;
        } else {
            int zz = zb - 16;
            for (int i = threadIdx.x; i < 128; i += 256) g_Z[zz * 128 + i] = 0.f;
        }
        return;
    }
    int tid = threadIdx.x;
#pragma unroll
    for (int i = 0; i < 16; i++) {
        int idx = tid + i * 256;          // idx = f*64 + e  (f = k/reduction dim)
        int f = idx >> 6, e = idx & 63;
        float lw = lnw[f];
        g_Wqf[idx] = Wq[e * 64 + f] * lw;
        g_Wkf[idx] = Wk[e * 64 + f] * lw;
        g_Wvf[idx] = Wv[e * 64 + f] * lw;
        g_Wof[idx] = Wo[e * 64 + f];      // WoT[k=e_att][fo]
    }
    if (tid < 64) {
        int e = tid;
        float dq = 0.f, cq = 0.f, dk = 0.f, ck = 0.f, dv = 0.f, cv = 0.f;
        for (int f = 0; f < 64; f++) {
            float lw = lnw[f], lb2 = lnb[f];
            float wq = Wq[e * 64 + f], wk = Wk[e * 64 + f], wv = Wv[e * 64 + f];
            dq += wq * lw;  cq = fmaf(lb2, wq, cq);
            dk += wk * lw;  ck = fmaf(lb2, wk, ck);
            dv += wv * lw;  cv = fmaf(lb2, wv, cv);
        }
        g_dq[e] = dq; g_cq[e] = cq + bq[e];
        g_dk[e] = dk; g_ck[e] = ck + bk[e];
        g_dv[e] = dv; g_cv[e] = cv + bv[e];
    }
}

// ---------------- RevIN stats per (b,f) ----------------
__global__ void __launch_bounds__(256) k_stats(const float* __restrict__ x) {
    int bf = blockIdx.x;
    const float4* p = (const float4*)(x + (size_t)bf * Ln);
    float s1 = 0.f, s2 = 0.f;
    for (int i = threadIdx.x; i < Ln / 4; i += 256) {
        float4 v = p[i];
        s1 += (v.x + v.y) + (v.z + v.w);
        s2 = fmaf(v.x, v.x, s2); s2 = fmaf(v.y, v.y, s2);
        s2 = fmaf(v.z, v.z, s2); s2 = fmaf(v.w, v.w, s2);
    }
    __shared__ float r1[256], r2[256];
    r1[threadIdx.x] = s1; r2[threadIdx.x] = s2;
    __syncthreads();
    for (int s = 128; s > 0; s >>= 1) {
        if (threadIdx.x < s) {
            r1[threadIdx.x] += r1[threadIdx.x + s];
            r2[threadIdx.x] += r2[threadIdx.x + s];
        }
        __syncthreads();
    }
    if (threadIdx.x == 0) {
        float S1 = r1[0], S2 = r2[0];
        float mean = S1 / (float)Ln;
        float var = (S2 - S1 * mean) / (float)(Ln - 1);
        var = fmaxf(var, 0.f);
        float stdp = sqrtf(var) + 1e-5f;
        g_mean[bf] = mean; g_stdp[bf] = stdp; g_istd[bf] = 1.f / stdp;
    }
}

// ---------------- kernel 2: fused K+V projections + KV,Z (512 threads) — R7 verbatim ----------------
__global__ void __launch_bounds__(512) k_kv(
    const float* __restrict__ x, const float* __restrict__ gamma, const float* __restrict__ beta)
{
    extern __shared__ float sm[];
    float* xns = sm;                     // 64*SR floats; later phi(K)
    float* vb  = sm + 64 * SR;           // 64*SR floats
    float* wv  = sm + 2 * 64 * SR;       // 4096 floats
    float* wk  = wv + 4096;              // 4096 floats
    __shared__ float mus[128], rss[128], As[64], Cs[64];
    __shared__ float dks[64], cks[64], dvs[64], cvs[64];

    int b = blockIdx.y, tid = threadIdx.x;
    int l0b = blockIdx.x * 128;

    if (tid < 64) {
        float a = gamma[tid] * g_istd[b * 64 + tid];
        As[tid] = a;
        Cs[tid] = beta[tid] - g_mean[b * 64 + tid] * a;
        dks[tid] = g_dk[tid]; cks[tid] = g_ck[tid];
        dvs[tid] = g_dv[tid]; cvs[tid] = g_cv[tid];
    }
#pragma unroll
    for (int i = 0; i < 2; i++) {
        ((float4*)wv)[tid + i * 512] = ((const float4*)g_Wvf)[tid + i * 512];
        ((float4*)wk)[tid + i * 512] = ((const float4*)g_Wkf)[tid + i * 512];
    }
    __syncthreads();
#pragma unroll
    for (int i = 0; i < 4; i++) {
        int idx = tid + i * 512;
        int f = idx >> 5, c = idx & 31;
        float4 v = *(const float4*)(x + ((size_t)(b * 64 + f)) * Ln + l0b + c * 4);
        float a = As[f], c0 = Cs[f];
        v.x = fmaf(v.x, a, c0); v.y = fmaf(v.y, a, c0);
        v.z = fmaf(v.z, a, c0); v.w = fmaf(v.w, a, c0);
        *(float4*)(xns + f * SR + c * 4) = v;
    }
    __syncthreads();
    if (tid < 128) {
        float s1 = 0.f, s2 = 0.f;
#pragma unroll
        for (int f = 0; f < 64; f++) { float t = xns[f * SR + tid]; s1 += t; s2 = fmaf(t, t, s2); }
        float mu = s1 * (1.f / 64.f);
        mus[tid] = mu;
        rss[tid] = rsqrtf(fmaf(-mu, mu, s2 * (1.f / 64.f)) + 1e-5f);
    }
    __syncthreads();

    int pg = (tid & 15) + 16 * (tid >> 8);
    int eg = (tid >> 4) & 15;
    int e0 = eg * 4;
    const float* hb = xns + 2 * pg;
    const float* wvp = wv + e0;
    const float* wkp = wk + e0;

    ull aV[4][2], aK[4][2];
#pragma unroll
    for (int i = 0; i < 4; i++) { aV[i][0] = aV[i][1] = aK[i][0] = aK[i][1] = 0ULL; }
#pragma unroll 8
    for (int k = 0; k < 64; k++) {
        ull h0 = *(const ull*)(hb + k * SR);
        ull h1 = *(const ull*)(hb + k * SR + 64);
        float4 v4 = *(const float4*)(wvp + k * 64);
        float4 k4 = *(const float4*)(wkp + k * 64);
        ull wvd[4] = {dup(v4.x), dup(v4.y), dup(v4.z), dup(v4.w)};
        ull wkd[4] = {dup(k4.x), dup(k4.y), dup(k4.z), dup(k4.w)};
#pragma unroll
        for (int i = 0; i < 4; i++) {
            fma2(aV[i][0], wvd[i], h0); fma2(aV[i][1], wvd[i], h1);
            fma2(aK[i][0], wkd[i], h0); fma2(aK[i][1], wkd[i], h1);
        }
    }

    float2 mu0 = upk(*(const ull*)(mus + 2 * pg));
    float2 mu1 = upk(*(const ull*)(mus + 2 * pg + 64));
    float2 rs0 = upk(*(const ull*)(rss + 2 * pg));
    float2 rs1 = upk(*(const ull*)(rss + 2 * pg + 64));

#pragma unroll
    for (int i = 0; i < 4; i++) {
        int e = e0 + i; float dv = dvs[e], cv = cvs[e];
        float2 s0 = upk(aV[i][0]), s1 = upk(aV[i][1]);
        *(ull*)(vb + e * SR + 2 * pg) =
            pk2(fmaf(rs0.x, s0.x - mu0.x * dv, cv), fmaf(rs0.y, s0.y - mu0.y * dv, cv));
        *(ull*)(vb + e * SR + 2 * pg + 64) =
            pk2(fmaf(rs1.x, s1.x - mu1.x * dv, cv), fmaf(rs1.y, s1.y - mu1.y * dv, cv));
    }
    ull kw[4][2];
#pragma unroll
    for (int i = 0; i < 4; i++) {
        int e = e0 + i; float dk = dks[e], ck = cks[e];
        float2 s0 = upk(aK[i][0]), s1 = upk(aK[i][1]);
        kw[i][0] = pk2(phi_fn(fmaf(rs0.x, s0.x - mu0.x * dk, ck)),
                       phi_fn(fmaf(rs0.y, s0.y - mu0.y * dk, ck)));
        kw[i][1] = pk2(phi_fn(fmaf(rs1.x, s1.x - mu1.x * dk, ck)),
                       phi_fn(fmaf(rs1.y, s1.y - mu1.y * dk, ck)));
    }
    __syncthreads();   // all GEMM reads of xns done
#pragma unroll
    for (int i = 0; i < 4; i++) {
        *(ull*)(xns + (e0 + i) * SR + 2 * pg)      = kw[i][0];
        *(ull*)(xns + (e0 + i) * SR + 2 * pg + 64) = kw[i][1];
    }
    __syncthreads();

    {
        int hh = tid >> 6;
        int d  = (tid >> 3) & 7;
        int e2 = tid & 7;
        const float* kr = xns + (hh * 8 + d) * SR;
        const float* vr = vb + (hh * 8 + e2) * SR;
        ull a = 0ULL;
#pragma unroll 8
        for (int j = 0; j < 128; j += 4) {
            ulonglong2 kk = *(const ulonglong2*)(kr + j);
            ulonglong2 vv = *(const ulonglong2*)(vr + j);
            fma2(a, kk.x, vv.x);
            fma2(a, kk.y, vv.y);
        }
        float2 t = upk(a);
        atomicAdd(&g_KV[(b * 8 + hh) * 64 + d * 8 + e2], t.x + t.y);
    }
    if (tid < 64) {
        const float* kr = xns + tid * SR;
        float s = 0.f;
#pragma unroll
        for (int j = 0; j < 128; j += 4) {
            float4 v = *(const float4*)(kr + j);
            s += (v.x + v.y) + (v.z + v.w);
        }
        atomicAdd(&g_Z[b * 64 + tid], s);
    }
}

// ---------------- kernel 3: Q, attention, Wo+residual, fused temporal (512 threads) ----------------
__global__ void __launch_bounds__(512) k_qo(
    const float* __restrict__ x, const float* __restrict__ gamma, const float* __restrict__ beta,
    const float* __restrict__ bo, const float* __restrict__ Wlin)
{
    extern __shared__ float sm[];
    float* wq  = sm;                    // 4096 floats (Wq, then WoT)
    float* xns = sm + 4096;             // 64*SR
    float* qb  = sm + 4096 + 64 * SR;   // 64*SR; later y tile (65-ull row stride)
    ull*   wy  = (ull*)qb;              // y: 64 rows x 65 ulls = 33280 B (region 33792 B)
    ull*   wlu = (ull*)sm;              // Wlin slab: 96 rows x 64 ulls = 49152 B over wq+xns
    __shared__ float mus[128], rss[128], As[64], Cs[64], dqs[64], cqs[64], bos[64];
    __shared__ float KVs[512], Zs[64];

    int b = blockIdx.y, tid = threadIdx.x;
    int l0b = blockIdx.x * 128;

    if (tid < 64) {
        float a = gamma[tid] * g_istd[b * 64 + tid];
        As[tid] = a;
        Cs[tid] = beta[tid] - g_mean[b * 64 + tid] * a;
        dqs[tid] = g_dq[tid]; cqs[tid] = g_cq[tid];
        bos[tid] = bo[tid];
        Zs[tid] = g_Z[b * 64 + tid];
    }
    KVs[tid] = g_KV[b * 512 + tid];
#pragma unroll
    for (int i = 0; i < 2; i++)
        ((float4*)wq)[tid + i * 512] = ((const float4*)g_Wqf)[tid + i * 512];
    __syncthreads();
#pragma unroll
    for (int i = 0; i < 4; i++) {
        int idx = tid + i * 512;
        int f = idx >> 5, c = idx & 31;
        float4 v = *(const float4*)(x + ((size_t)(b * 64 + f)) * Ln + l0b + c * 4);
        float a = As[f], c0 = Cs[f];
        v.x = fmaf(v.x, a, c0); v.y = fmaf(v.y, a, c0);
        v.z = fmaf(v.z, a, c0); v.w = fmaf(v.w, a, c0);
        *(float4*)(xns + f * SR + c * 4) = v;
    }
    __syncthreads();
    if (tid < 128) {
        float s1 = 0.f, s2 = 0.f;
#pragma unroll
        for (int f = 0; f < 64; f++) { float t = xns[f * SR + tid]; s1 += t; s2 = fmaf(t, t, s2); }
        float mu = s1 * (1.f / 64.f);
        mus[tid] = mu;
        rss[tid] = rsqrtf(fmaf(-mu, mu, s2 * (1.f / 64.f)) + 1e-5f);
    }
    __syncthreads();

    int pg = (tid & 15) + 16 * (tid >> 8);
    int eg = (tid >> 4) & 15;
    int e0 = eg * 4;

    float2 mu0 = upk(*(const ull*)(mus + 2 * pg));
    float2 mu1 = upk(*(const ull*)(mus + 2 * pg + 64));
    float2 rs0 = upk(*(const ull*)(rss + 2 * pg));
    float2 rs1 = upk(*(const ull*)(rss + 2 * pg + 64));

    // ---- Q GEMM -> phi -> qb ----
    {
        const float* hb = xns + 2 * pg;
        const float* wp = wq + e0;
        ull a[4][2];
#pragma unroll
        for (int i = 0; i < 4; i++) { a[i][0] = a[i][1] = 0ULL; }
#pragma unroll 8
        for (int k = 0; k < 64; k++) {
            ull h0 = *(const ull*)(hb + k * SR);
            ull h1 = *(const ull*)(hb + k * SR + 64);
            float4 w4 = *(const float4*)(wp + k * 64);
            ull wd[4] = {dup(w4.x), dup(w4.y), dup(w4.z), dup(w4.w)};
#pragma unroll
            for (int i = 0; i < 4; i++) {
                fma2(a[i][0], wd[i], h0);
                fma2(a[i][1], wd[i], h1);
            }
        }
#pragma unroll
        for (int i = 0; i < 4; i++) {
            int e = e0 + i; float dq = dqs[e], cq = cqs[e];
            float2 s0 = upk(a[i][0]), s1 = upk(a[i][1]);
            *(ull*)(qb + e * SR + 2 * pg) =
                pk2(phi_fn(fmaf(rs0.x, s0.x - mu0.x * dq, cq)),
                    phi_fn(fmaf(rs0.y, s0.y - mu0.y * dq, cq)));
            *(ull*)(qb + e * SR + 2 * pg + 64) =
                pk2(phi_fn(fmaf(rs1.x, s1.x - mu1.x * dq, cq)),
                    phi_fn(fmaf(rs1.y, s1.y - mu1.y * dq, cq)));
        }
    }
    __syncthreads();   // q complete; Wq reads done

    // ---- reload w <- WoT; attention (2 heads per thread, own cells) ----
#pragma unroll
    for (int i = 0; i < 2; i++)
        ((float4*)wq)[tid + i * 512] = ((const float4*)g_Wof)[tid + i * 512];
    {
        int la = tid & 127;
        int hgrp = tid >> 7;   // 0..3
#pragma unroll
        for (int t = 0; t < 2; t++) {
            int hh = hgrp * 2 + t;
            float q[8];
#pragma unroll
            for (int d = 0; d < 8; d++) q[d] = qb[(hh * 8 + d) * SR + la];
            float nrm = 1e-6f;
#pragma unroll
            for (int d = 0; d < 8; d++) nrm = fmaf(q[d], Zs[hh * 8 + d], nrm);
            float inv = 1.f / nrm;
#pragma unroll
            for (int j = 0; j < 8; j++) {
                float s = 0.f;
#pragma unroll
                for (int d = 0; d < 8; d++) s = fmaf(q[d], KVs[hh * 64 + d * 8 + j], s);
                qb[(hh * 8 + j) * SR + la] = s * inv;
            }
        }
    }
    __syncthreads();

    // ---- Wo GEMM + bias + residual -> y (65-ull stride over qb region) ----
    {
        const float* hb = qb + 2 * pg;
        const float* wp = wq + e0;
        ull a[4][2];
#pragma unroll
        for (int i = 0; i < 4; i++) { a[i][0] = a[i][1] = 0ULL; }
#pragma unroll 8
        for (int k = 0; k < 64; k++) {
            ull h0 = *(const ull*)(hb + k * SR);
            ull h1 = *(const ull*)(hb + k * SR + 64);
            float4 w4 = *(const float4*)(wp + k * 64);
            ull wd[4] = {dup(w4.x), dup(w4.y), dup(w4.z), dup(w4.w)};
#pragma unroll
            for (int i = 0; i < 4; i++) {
                fma2(a[i][0], wd[i], h0);
                fma2(a[i][1], wd[i], h1);
            }
        }
        ull yo[4][2];
#pragma unroll
        for (int i = 0; i < 4; i++) {
            int fo = e0 + i;
            float bb = bos[fo];
            float2 r0 = upk(*(const ull*)(xns + fo * SR + 2 * pg));
            float2 r1 = upk(*(const ull*)(xns + fo * SR + 2 * pg + 64));
            float2 s0 = upk(a[i][0]), s1 = upk(a[i][1]);
            yo[i][0] = pk2(s0.x + bb + r0.x, s0.y + bb + r0.y);
            yo[i][1] = pk2(s1.x + bb + r1.x, s1.y + bb + r1.y);
        }
        __syncthreads();   // all Wo GEMM reads of qb done
#pragma unroll
        for (int i = 0; i < 4; i++) {
            wy[(e0 + i) * 65 + pg]      = yo[i][0];
            wy[(e0 + i) * 65 + pg + 32] = yo[i][1];
        }
    }
    __syncthreads();   // y complete; residual reads of xns done

    // ---- Wlin slab (96 x 128 floats, contiguous) into wq+xns region ----
#pragma unroll
    for (int i = 0; i < 6; i++) {
        int idx = tid + i * 512;               // 3072 float4 = 96 rows x 32
        int p = idx >> 5, c4 = idx & 31;
        ((float4*)wlu)[(p << 5) + c4] = *(const float4*)(Wlin + (size_t)p * Ln + l0b + c4 * 4);
    }
    __syncthreads();

    // ---- temporal GEMM: M[b,p,f] += sum_l Wlin[p,l] * y[f,l] ----
    // y rows at 65-ull (520 B) stride: 16 fg lanes -> banks 2*fg mod 32, conflict-free LDS.64
    int fg = tid & 15, pg2 = tid >> 4;          // 16 f-groups x 32 p-groups
    ull acc2[3][4];
#pragma unroll
    for (int i = 0; i < 3; i++)
#pragma unroll
        for (int k = 0; k < 4; k++) acc2[i][k] = 0ULL;
#pragma unroll 4
    for (int j = 0; j < 64; j += 2) {
        ull yv0[4], yv1[4];
        ulonglong2 wvv[3];
#pragma unroll
        for (int k = 0; k < 4; k++) {
            const ull* yr = wy + (fg + 16 * k) * 65 + j;
            yv0[k] = yr[0];
            yv1[k] = yr[1];
        }
#pragma unroll
        for (int i = 0; i < 3; i++) wvv[i] = *(const ulonglong2*)(wlu + (pg2 + 32 * i) * 64 + j);
#pragma unroll
        for (int i = 0; i < 3; i++)
#pragma unroll
            for (int k = 0; k < 4; k++) {
                fma2(acc2[i][k], wvv[i].x, yv0[k]);
                fma2(acc2[i][k], wvv[i].y, yv1[k]);
            }
    }
#pragma unroll
    for (int i = 0; i < 3; i++)
#pragma unroll
        for (int k = 0; k < 4; k++) {
            float2 t = upk(acc2[i][k]);
            atomicAdd(&g_M[(b * 96 + pg2 + 32 * i) * 64 + fg + 16 * k], t.x + t.y);
        }
}

// ---------------- kernel 5: denorm + projector ----------------
__global__ void k_epi(const float* __restrict__ gamma, const float* __restrict__ beta,
                      const float* __restrict__ blin, const float* __restrict__ Wp,
                      const float* __restrict__ bp, float* __restrict__ out) {
    int b = blockIdx.x, p = threadIdx.x;
    float bl = blin[p];
    float s = bp[0];
#pragma unroll
    for (int f = 0; f < 64; f++) {
        float y = g_M[(b * 96 + p) * 64 + f] + bl;
        y = (y - beta[f]) / gamma[f];
        y = fmaf(y, g_stdp[b * 64 + f], g_mean[b * 64 + f]);
        s = fmaf(y, Wp[f], s);
    }
    out[b * 96 + p] = s;
}

// ---------------- launch ----------------
extern "C" void kernel_launch(void* const* d_in, const int* in_sizes, int n_in,
                              void* d_out, int out_size) {
    (void)in_sizes; (void)n_in; (void)out_size;
    const float* x     = (const float*)d_in[0];
    const float* gamma = (const float*)d_in[1];
    const float* beta  = (const float*)d_in[2];
    const float* lnw   = (const float*)d_in[3];
    const float* lnb   = (const float*)d_in[4];
    const float* Wq    = (const float*)d_in[5];
    const float* bq    = (const float*)d_in[6];
    const float* Wk    = (const float*)d_in[7];
    const float* bk    = (const float*)d_in[8];
    const float* Wv    = (const float*)d_in[9];
    const float* bv    = (const float*)d_in[10];
    const float* Wo    = (const float*)d_in[11];
    const float* bo    = (const float*)d_in[12];
    const float* Wlin  = (const float*)d_in[13];
    const float* blin  = (const float*)d_in[14];
    const float* Wp    = (const float*)d_in[15];
    const float* bp    = (const float*)d_in[16];
    float* out = (float*)d_out;

    const int SMB_KV = (2 * 64 * SR + 8192) * 4;   // 100352 B
    const int SMB_QO = (4096 + 2 * 64 * SR) * 4;   // 83968 B
    cudaFuncSetAttribute(k_kv, cudaFuncAttributeMaxDynamicSharedMemorySize, SMB_KV);
    cudaFuncSetAttribute(k_qo, cudaFuncAttributeMaxDynamicSharedMemorySize, SMB_QO);

    k_prep<<<33, 256>>>(lnw, lnb, Wq, bq, Wk, bk, Wv, bv, Wo);
    k_stats<<<Bn * Fn, 256>>>(x);
    k_kv<<<dim3(Ln / 128, Bn), 512, SMB_KV>>>(x, gamma, beta);
    k_qo<<<dim3(Ln / 128, Bn), 512, SMB_QO>>>(x, gamma, beta, bo, Wlin);
    k_epi<<<Bn, Pn>>>(gamma, beta, blin, Wp, bp, out);
}

// round 12
// speedup vs baseline: 1.3479x; 1.1014x over previous
#include <cuda_runtime.h>
#include <cstdint>

#define Bn 32
#define Fn 64
#define Ln 8192
#define Pn 96
#define SR 132    // data tile row stride (floats)

typedef unsigned long long ull;

// ---------------- scratch (device globals) ----------------
__device__ float g_mean[Bn * Fn];
__device__ float g_istd[Bn * Fn];
__device__ float g_stdp[Bn * Fn];
__device__ float g_KV[Bn * 512];
__device__ float g_Z[Bn * 64];
__device__ float g_M[Bn * Pn * Fn];
// pre-folded plain-float weights, layout [k(=input dim)][e(=output dim)]
__device__ float g_Wqf[4096], g_Wkf[4096], g_Wvf[4096], g_Wof[4096];
__device__ float g_dq[64], g_cq[64], g_dk[64], g_ck[64], g_dv[64], g_cv[64];

// ---------------- helpers ----------------
__device__ __forceinline__ void fma2(ull& d, ull a, ull b) {
    asm("fma.rn.f32x2 %0, %1, %2, %0;" : "+l"(d) : "l"(a), "l"(b));
}
__device__ __forceinline__ float2 upk(ull v) {
    float2 r;
    asm("mov.b64 {%0, %1}, %2;" : "=f"(r.x), "=f"(r.y) : "l"(v));
    return r;
}
__device__ __forceinline__ ull pk2(float a, float b) {
    ull r;
    asm("mov.b64 %0, {%1, %2};" : "=l"(r) : "f"(a), "f"(b));
    return r;
}
__device__ __forceinline__ ull dup(float a) { return pk2(a, a); }
__device__ __forceinline__ float phi_fn(float v) {
    return v > 0.f ? v + 1.f : __expf(v);   // elu(x)+1
}

// ---------------- prep (block 0) + zero accumulators (blocks 1..32) ----------------
__global__ void __launch_bounds__(256) k_prep(
    const float* __restrict__ lnw, const float* __restrict__ lnb,
    const float* __restrict__ Wq, const float* __restrict__ bq,
    const float* __restrict__ Wk, const float* __restrict__ bk,
    const float* __restrict__ Wv, const float* __restrict__ bv,
    const float* __restrict__ Wo)
{
    if (blockIdx.x > 0) {
        int zb = blockIdx.x - 1;
        int base = zb * 6144;
        for (int i = threadIdx.x; i < 6144; i += 256) g_M[base + i] = 0.f;
        if (zb < 16) {
            for (int i = threadIdx.x; i < 1024; i += 256) g_KV[zb * 1024 + i] = 0.f;
        } else {
            int zz = zb - 16;
            for (int i = threadIdx.x; i < 128; i += 256) g_Z[zz * 128 + i] = 0.f;
        }
        return;
    }
    int tid = threadIdx.x;
#pragma unroll
    for (int i = 0; i < 16; i++) {
        int idx = tid + i * 256;          // idx = f*64 + e
        int f = idx >> 6, e = idx & 63;
        float lw = lnw[f];
        g_Wqf[idx] = Wq[e * 64 + f] * lw;
        g_Wkf[idx] = Wk[e * 64 + f] * lw;
        g_Wvf[idx] = Wv[e * 64 + f] * lw;
        g_Wof[idx] = Wo[e * 64 + f];      // WoT[k=e_att][fo]
    }
    if (tid < 64) {
        int e = tid;
        float dq = 0.f, cq = 0.f, dk = 0.f, ck = 0.f, dv = 0.f, cv = 0.f;
        for (int f = 0; f < 64; f++) {
            float lw = lnw[f], lb2 = lnb[f];
            float wq = Wq[e * 64 + f], wk = Wk[e * 64 + f], wv = Wv[e * 64 + f];
            dq += wq * lw;  cq = fmaf(lb2, wq, cq);
            dk += wk * lw;  ck = fmaf(lb2, wk, ck);
            dv += wv * lw;  cv = fmaf(lb2, wv, cv);
        }
        g_dq[e] = dq; g_cq[e] = cq + bq[e];
        g_dk[e] = dk; g_ck[e] = ck + bk[e];
        g_dv[e] = dv; g_cv[e] = cv + bv[e];
    }
}

// ---------------- RevIN stats per (b,f) ----------------
__global__ void __launch_bounds__(256) k_stats(const float* __restrict__ x) {
    int bf = blockIdx.x;
    const float4* p = (const float4*)(x + (size_t)bf * Ln);
    float s1 = 0.f, s2 = 0.f;
    for (int i = threadIdx.x; i < Ln / 4; i += 256) {
        float4 v = p[i];
        s1 += (v.x + v.y) + (v.z + v.w);
        s2 = fmaf(v.x, v.x, s2); s2 = fmaf(v.y, v.y, s2);
        s2 = fmaf(v.z, v.z, s2); s2 = fmaf(v.w, v.w, s2);
    }
    __shared__ float r1[256], r2[256];
    r1[threadIdx.x] = s1; r2[threadIdx.x] = s2;
    __syncthreads();
    for (int s = 128; s > 0; s >>= 1) {
        if (threadIdx.x < s) {
            r1[threadIdx.x] += r1[threadIdx.x + s];
            r2[threadIdx.x] += r2[threadIdx.x + s];
        }
        __syncthreads();
    }
    if (threadIdx.x == 0) {
        float S1 = r1[0], S2 = r2[0];
        float mean = S1 / (float)Ln;
        float var = (S2 - S1 * mean) / (float)(Ln - 1);
        var = fmaxf(var, 0.f);
        float stdp = sqrtf(var) + 1e-5f;
        g_mean[bf] = mean; g_stdp[bf] = stdp; g_istd[bf] = 1.f / stdp;
    }
}

// ---------------- kernel 2: fused K+V projections + KV,Z (256 threads, 4e x 8l) ----------------
__global__ void __launch_bounds__(256, 2) k_kv(
    const float* __restrict__ x, const float* __restrict__ gamma, const float* __restrict__ beta)
{
    extern __shared__ float sm[];
    float* xns = sm;                     // 64*SR; later phi(K)
    float* vb  = sm + 64 * SR;           // 64*SR
    float* wv  = sm + 2 * 64 * SR;       // 4096 floats
    float* wk  = wv + 4096;              // 4096 floats
    __shared__ float mus[128], rss[128], As[64], Cs[64];
    __shared__ float dks[64], cks[64], dvs[64], cvs[64];

    int b = blockIdx.y, tid = threadIdx.x;
    int l0b = blockIdx.x * 128;

    if (tid < 64) {
        float a = gamma[tid] * g_istd[b * 64 + tid];
        As[tid] = a;
        Cs[tid] = beta[tid] - g_mean[b * 64 + tid] * a;
        dks[tid] = g_dk[tid]; cks[tid] = g_ck[tid];
        dvs[tid] = g_dv[tid]; cvs[tid] = g_cv[tid];
    }
#pragma unroll
    for (int i = 0; i < 4; i++) {
        ((float4*)wv)[tid + i * 256] = ((const float4*)g_Wvf)[tid + i * 256];
        ((float4*)wk)[tid + i * 256] = ((const float4*)g_Wkf)[tid + i * 256];
    }
    __syncthreads();
#pragma unroll
    for (int i = 0; i < 8; i++) {
        int idx = tid + i * 256;
        int f = idx >> 5, c = idx & 31;
        float4 v = *(const float4*)(x + ((size_t)(b * 64 + f)) * Ln + l0b + c * 4);
        float a = As[f], c0 = Cs[f];
        v.x = fmaf(v.x, a, c0); v.y = fmaf(v.y, a, c0);
        v.z = fmaf(v.z, a, c0); v.w = fmaf(v.w, a, c0);
        *(float4*)(xns + f * SR + c * 4) = v;
    }
    __syncthreads();
    if (tid < 128) {
        float s1 = 0.f, s2 = 0.f;
#pragma unroll
        for (int f = 0; f < 64; f++) { float t = xns[f * SR + tid]; s1 += t; s2 = fmaf(t, t, s2); }
        float mu = s1 * (1.f / 64.f);
        mus[tid] = mu;
        rss[tid] = rsqrtf(fmaf(-mu, mu, s2 * (1.f / 64.f)) + 1e-5f);
    }
    __syncthreads();

    // thread tile: 4 e x 8 l (l-pairs at 2*lg + 32*p)
    int lg = tid & 15, eg = tid >> 4;
    int e0 = eg * 4;
    const float* hb = xns + 2 * lg;
    const float* wvp = wv + e0;
    const float* wkp = wk + e0;

    ull aV[4][4], aK[4][4];
#pragma unroll
    for (int i = 0; i < 4; i++)
#pragma unroll
        for (int p = 0; p < 4; p++) { aV[i][p] = 0ULL; aK[i][p] = 0ULL; }

#pragma unroll 4
    for (int k = 0; k < 64; k++) {
        ull h[4];
        h[0] = *(const ull*)(hb + k * SR);
        h[1] = *(const ull*)(hb + k * SR + 32);
        h[2] = *(const ull*)(hb + k * SR + 64);
        h[3] = *(const ull*)(hb + k * SR + 96);
        float4 v4 = *(const float4*)(wvp + k * 64);
        float4 k4 = *(const float4*)(wkp + k * 64);
        ull wvd[4] = {dup(v4.x), dup(v4.y), dup(v4.z), dup(v4.w)};
        ull wkd[4] = {dup(k4.x), dup(k4.y), dup(k4.z), dup(k4.w)};
#pragma unroll
        for (int i = 0; i < 4; i++)
#pragma unroll
            for (int p = 0; p < 4; p++) {
                fma2(aV[i][p], wvd[i], h[p]);
                fma2(aK[i][p], wkd[i], h[p]);
            }
    }

    float2 muv[4], rsv[4];
#pragma unroll
    for (int p = 0; p < 4; p++) {
        muv[p] = upk(*(const ull*)(mus + 2 * lg + 32 * p));
        rsv[p] = upk(*(const ull*)(rss + 2 * lg + 32 * p));
    }

    // ---- V epilogue -> vb ----
#pragma unroll
    for (int i = 0; i < 4; i++) {
        int e = e0 + i; float dv = dvs[e], cv = cvs[e];
#pragma unroll
        for (int p = 0; p < 4; p++) {
            float2 s = upk(aV[i][p]);
            *(ull*)(vb + e * SR + 2 * lg + 32 * p) =
                pk2(fmaf(rsv[p].x, s.x - muv[p].x * dv, cv),
                    fmaf(rsv[p].y, s.y - muv[p].y * dv, cv));
        }
    }
    // ---- K epilogue: phi in regs ----
    ull kw[4][4];
#pragma unroll
    for (int i = 0; i < 4; i++) {
        int e = e0 + i; float dk = dks[e], ck = cks[e];
#pragma unroll
        for (int p = 0; p < 4; p++) {
            float2 s = upk(aK[i][p]);
            kw[i][p] = pk2(phi_fn(fmaf(rsv[p].x, s.x - muv[p].x * dk, ck)),
                           phi_fn(fmaf(rsv[p].y, s.y - muv[p].y * dk, ck)));
        }
    }
    __syncthreads();   // all GEMM reads of xns done
#pragma unroll
    for (int i = 0; i < 4; i++)
#pragma unroll
        for (int p = 0; p < 4; p++)
            *(ull*)(xns + (e0 + i) * SR + 2 * lg + 32 * p) = kw[i][p];
    __syncthreads();

    // ---- KV accumulation: two (hh,d,e) entries per thread ----
    {
        int hh = tid >> 5;
        int rem = tid & 31;
        int d  = rem >> 2;
        int e2 = (rem & 3) * 2;
        const float* kr  = xns + (hh * 8 + d) * SR;
        const float* vr0 = vb + (hh * 8 + e2) * SR;
        const float* vr1 = vr0 + SR;
        ull a0 = 0ULL, a1 = 0ULL;
#pragma unroll 8
        for (int j = 0; j < 128; j += 4) {
            ulonglong2 kk = *(const ulonglong2*)(kr + j);
            ulonglong2 v0 = *(const ulonglong2*)(vr0 + j);
            ulonglong2 v1 = *(const ulonglong2*)(vr1 + j);
            fma2(a0, kk.x, v0.x); fma2(a0, kk.y, v0.y);
            fma2(a1, kk.x, v1.x); fma2(a1, kk.y, v1.y);
        }
        float2 t0 = upk(a0), t1 = upk(a1);
        atomicAdd(&g_KV[(b * 8 + hh) * 64 + d * 8 + e2],     t0.x + t0.y);
        atomicAdd(&g_KV[(b * 8 + hh) * 64 + d * 8 + e2 + 1], t1.x + t1.y);
    }
    if (tid < 64) {
        const float* kr = xns + tid * SR;
        float s = 0.f;
#pragma unroll
        for (int j = 0; j < 128; j += 4) {
            float4 v = *(const float4*)(kr + j);
            s += (v.x + v.y) + (v.z + v.w);
        }
        atomicAdd(&g_Z[b * 64 + tid], s);
    }
}

// ---------------- kernel 3: Q, attention, Wo+residual, fused temporal (256 threads) ----------------
__global__ void __launch_bounds__(256, 2) k_qo(
    const float* __restrict__ x, const float* __restrict__ gamma, const float* __restrict__ beta,
    const float* __restrict__ bo, const float* __restrict__ Wlin)
{
    extern __shared__ float sm[];
    float* wq  = sm;                    // 4096 floats (Wq, then WoT)
    float* xns = sm + 4096;             // 64*SR
    float* qb  = sm + 4096 + 64 * SR;   // 64*SR; later y tile (65-ull row stride)
    ull*   wy  = (ull*)qb;              // y: 64 rows x 65 ulls = 33280 B (region 33792 B)
    ull*   wlu = (ull*)sm;              // Wlin slab: 96 rows x 64 ulls = 49152 B over wq+xns
    __shared__ float mus[128], rss[128], As[64], Cs[64], dqs[64], cqs[64], bos[64];
    __shared__ __align__(16) float KVs[512];
    __shared__ float Zs[64];

    int b = blockIdx.y, tid = threadIdx.x;
    int l0b = blockIdx.x * 128;

    if (tid < 64) {
        float a = gamma[tid] * g_istd[b * 64 + tid];
        As[tid] = a;
        Cs[tid] = beta[tid] - g_mean[b * 64 + tid] * a;
        dqs[tid] = g_dq[tid]; cqs[tid] = g_cq[tid];
        bos[tid] = bo[tid];
        Zs[tid] = g_Z[b * 64 + tid];
    }
    KVs[tid] = g_KV[b * 512 + tid];
    KVs[tid + 256] = g_KV[b * 512 + 256 + tid];
#pragma unroll
    for (int i = 0; i < 4; i++)
        ((float4*)wq)[tid + i * 256] = ((const float4*)g_Wqf)[tid + i * 256];
    __syncthreads();
#pragma unroll
    for (int i = 0; i < 8; i++) {
        int idx = tid + i * 256;
        int f = idx >> 5, c = idx & 31;
        float4 v = *(const float4*)(x + ((size_t)(b * 64 + f)) * Ln + l0b + c * 4);
        float a = As[f], c0 = Cs[f];
        v.x = fmaf(v.x, a, c0); v.y = fmaf(v.y, a, c0);
        v.z = fmaf(v.z, a, c0); v.w = fmaf(v.w, a, c0);
        *(float4*)(xns + f * SR + c * 4) = v;
    }
    __syncthreads();
    if (tid < 128) {
        float s1 = 0.f, s2 = 0.f;
#pragma unroll
        for (int f = 0; f < 64; f++) { float t = xns[f * SR + tid]; s1 += t; s2 = fmaf(t, t, s2); }
        float mu = s1 * (1.f / 64.f);
        mus[tid] = mu;
        rss[tid] = rsqrtf(fmaf(-mu, mu, s2 * (1.f / 64.f)) + 1e-5f);
    }
    __syncthreads();

    int lg = tid & 15, eg = tid >> 4;
    int e0 = eg * 4;
    const float* wqp = wq + e0;

    float2 muv[4], rsv[4];
#pragma unroll
    for (int p = 0; p < 4; p++) {
        muv[p] = upk(*(const ull*)(mus + 2 * lg + 32 * p));
        rsv[p] = upk(*(const ull*)(rss + 2 * lg + 32 * p));
    }

    // ---- Q GEMM (4e x 8l) -> phi -> qb ----
    {
        const float* hb = xns + 2 * lg;
        ull a[4][4];
#pragma unroll
        for (int i = 0; i < 4; i++)
#pragma unroll
            for (int p = 0; p < 4; p++) a[i][p] = 0ULL;
#pragma unroll 4
        for (int k = 0; k < 64; k++) {
            ull h[4];
            h[0] = *(const ull*)(hb + k * SR);
            h[1] = *(const ull*)(hb + k * SR + 32);
            h[2] = *(const ull*)(hb + k * SR + 64);
            h[3] = *(const ull*)(hb + k * SR + 96);
            float4 w4 = *(const float4*)(wqp + k * 64);
            ull wd[4] = {dup(w4.x), dup(w4.y), dup(w4.z), dup(w4.w)};
#pragma unroll
            for (int i = 0; i < 4; i++)
#pragma unroll
                for (int p = 0; p < 4; p++) fma2(a[i][p], wd[i], h[p]);
        }
#pragma unroll
        for (int i = 0; i < 4; i++) {
            int e = e0 + i; float dq = dqs[e], cq = cqs[e];
#pragma unroll
            for (int p = 0; p < 4; p++) {
                float2 s = upk(a[i][p]);
                *(ull*)(qb + e * SR + 2 * lg + 32 * p) =
                    pk2(phi_fn(fmaf(rsv[p].x, s.x - muv[p].x * dq, cq)),
                        phi_fn(fmaf(rsv[p].y, s.y - muv[p].y * dq, cq)));
            }
        }
    }
    __syncthreads();   // q complete; Wq reads done

    // ---- reload w <- WoT; attention (4 heads per thread, vectorized KV) ----
#pragma unroll
    for (int i = 0; i < 4; i++)
        ((float4*)wq)[tid + i * 256] = ((const float4*)g_Wof)[tid + i * 256];
    {
        int la = tid & 127;
        int hgrp = tid >> 7;   // 0..1
#pragma unroll
        for (int t = 0; t < 4; t++) {
            int hh = hgrp * 4 + t;
            float q[8];
#pragma unroll
            for (int d = 0; d < 8; d++) q[d] = qb[(hh * 8 + d) * SR + la];
            float nrm = 1e-6f;
#pragma unroll
            for (int d = 0; d < 8; d++) nrm = fmaf(q[d], Zs[hh * 8 + d], nrm);
            float inv = 1.f / nrm;
            float s[8] = {0.f, 0.f, 0.f, 0.f, 0.f, 0.f, 0.f, 0.f};
#pragma unroll
            for (int d = 0; d < 8; d++) {
                float4 kv0 = *(const float4*)(KVs + hh * 64 + d * 8);
                float4 kv1 = *(const float4*)(KVs + hh * 64 + d * 8 + 4);
                float qd = q[d];
                s[0] = fmaf(qd, kv0.x, s[0]); s[1] = fmaf(qd, kv0.y, s[1]);
                s[2] = fmaf(qd, kv0.z, s[2]); s[3] = fmaf(qd, kv0.w, s[3]);
                s[4] = fmaf(qd, kv1.x, s[4]); s[5] = fmaf(qd, kv1.y, s[5]);
                s[6] = fmaf(qd, kv1.z, s[6]); s[7] = fmaf(qd, kv1.w, s[7]);
            }
#pragma unroll
            for (int j = 0; j < 8; j++)
                qb[(hh * 8 + j) * SR + la] = s[j] * inv;
        }
    }
    __syncthreads();

    // ---- Wo GEMM + bias + residual -> y (65-ull stride over qb region) ----
    {
        const float* hb = qb + 2 * lg;
        ull a[4][4];
#pragma unroll
        for (int i = 0; i < 4; i++)
#pragma unroll
            for (int p = 0; p < 4; p++) a[i][p] = 0ULL;
#pragma unroll 4
        for (int k = 0; k < 64; k++) {
            ull h[4];
            h[0] = *(const ull*)(hb + k * SR);
            h[1] = *(const ull*)(hb + k * SR + 32);
            h[2] = *(const ull*)(hb + k * SR + 64);
            h[3] = *(const ull*)(hb + k * SR + 96);
            float4 w4 = *(const float4*)(wqp + k * 64);
            ull wd[4] = {dup(w4.x), dup(w4.y), dup(w4.z), dup(w4.w)};
#pragma unroll
            for (int i = 0; i < 4; i++)
#pragma unroll
                for (int p = 0; p < 4; p++) fma2(a[i][p], wd[i], h[p]);
        }
        ull yo[4][4];
#pragma unroll
        for (int i = 0; i < 4; i++) {
            int fo = e0 + i;
            float bb = bos[fo];
#pragma unroll
            for (int p = 0; p < 4; p++) {
                float2 r = upk(*(const ull*)(xns + fo * SR + 2 * lg + 32 * p));
                float2 s = upk(a[i][p]);
                yo[i][p] = pk2(s.x + bb + r.x, s.y + bb + r.y);
            }
        }
        __syncthreads();   // Wo GEMM qb-reads + residual xns-reads done
#pragma unroll
        for (int i = 0; i < 4; i++)
#pragma unroll
            for (int p = 0; p < 4; p++)
                wy[(e0 + i) * 65 + lg + 16 * p] = yo[i][p];
    }
    __syncthreads();   // y complete

    // ---- Wlin slab (96 x 128 floats, contiguous) into wq+xns region ----
#pragma unroll
    for (int i = 0; i < 12; i++) {
        int idx = tid + i * 256;               // 3072 float4 = 96 rows x 32
        int p = idx >> 5, c4 = idx & 31;
        ((float4*)wlu)[(p << 5) + c4] = *(const float4*)(Wlin + (size_t)p * Ln + l0b + c4 * 4);
    }
    __syncthreads();

    // ---- temporal GEMM: M[b,p,f] += sum_l Wlin[p,l] * y[f,l] ----
    int fg = tid & 15, pg2 = tid >> 4;          // 16 f-groups x 16 p-groups
    ull acc2[6][4];
#pragma unroll
    for (int i = 0; i < 6; i++)
#pragma unroll
        for (int k = 0; k < 4; k++) acc2[i][k] = 0ULL;
#pragma unroll 4
    for (int j = 0; j < 64; j += 2) {
        ull yv0[4], yv1[4];
        ulonglong2 wvv[6];
#pragma unroll
        for (int k = 0; k < 4; k++) {
            const ull* yr = wy + (fg + 16 * k) * 65 + j;
            yv0[k] = yr[0];
            yv1[k] = yr[1];
        }
#pragma unroll
        for (int i = 0; i < 6; i++) wvv[i] = *(const ulonglong2*)(wlu + (pg2 + 16 * i) * 64 + j);
#pragma unroll
        for (int i = 0; i < 6; i++)
#pragma unroll
            for (int k = 0; k < 4; k++) {
                fma2(acc2[i][k], wvv[i].x, yv0[k]);
                fma2(acc2[i][k], wvv[i].y, yv1[k]);
            }
    }
#pragma unroll
    for (int i = 0; i < 6; i++)
#pragma unroll
        for (int k = 0; k < 4; k++) {
            float2 t = upk(acc2[i][k]);
            atomicAdd(&g_M[(b * 96 + pg2 + 16 * i) * 64 + fg + 16 * k], t.x + t.y);
        }
}

// ---------------- kernel 5: denorm + projector ----------------
__global__ void k_epi(const float* __restrict__ gamma, const float* __restrict__ beta,
                      const float* __restrict__ blin, const float* __restrict__ Wp,
                      const float* __restrict__ bp, float* __restrict__ out) {
    int b = blockIdx.x, p = threadIdx.x;
    float bl = blin[p];
    float s = bp[0];
#pragma unroll
    for (int f = 0; f < 64; f++) {
        float y = g_M[(b * 96 + p) * 64 + f] + bl;
        y = (y - beta[f]) / gamma[f];
        y = fmaf(y, g_stdp[b * 64 + f], g_mean[b * 64 + f]);
        s = fmaf(y, Wp[f], s);
    }
    out[b * 96 + p] = s;
}

// ---------------- launch ----------------
extern "C" void kernel_launch(void* const* d_in, const int* in_sizes, int n_in,
                              void* d_out, int out_size) {
    (void)in_sizes; (void)n_in; (void)out_size;
    const float* x     = (const float*)d_in[0];
    const float* gamma = (const float*)d_in[1];
    const float* beta  = (const float*)d_in[2];
    const float* lnw   = (const float*)d_in[3];
    const float* lnb   = (const float*)d_in[4];
    const float* Wq    = (const float*)d_in[5];
    const float* bq    = (const float*)d_in[6];
    const float* Wk    = (const float*)d_in[7];
    const float* bk    = (const float*)d_in[8];
    const float* Wv    = (const float*)d_in[9];
    const float* bv    = (const float*)d_in[10];
    const float* Wo    = (const float*)d_in[11];
    const float* bo    = (const float*)d_in[12];
    const float* Wlin  = (const float*)d_in[13];
    const float* blin  = (const float*)d_in[14];
    const float* Wp    = (const float*)d_in[15];
    const float* bp    = (const float*)d_in[16];
    float* out = (float*)d_out;

    const int SMB_KV = (2 * 64 * SR + 8192) * 4;   // 100352 B
    const int SMB_QO = (4096 + 2 * 64 * SR) * 4;   // 83968 B
    cudaFuncSetAttribute(k_kv, cudaFuncAttributeMaxDynamicSharedMemorySize, SMB_KV);
    cudaFuncSetAttribute(k_qo, cudaFuncAttributeMaxDynamicSharedMemorySize, SMB_QO);

    k_prep<<<33, 256>>>(lnw, lnb, Wq, bq, Wk, bk, Wv, bv, Wo);
    k_stats<<<Bn * Fn, 256>>>(x);
    k_kv<<<dim3(Ln / 128, Bn), 256, SMB_KV>>>(x, gamma, beta);
    k_qo<<<dim3(Ln / 128, Bn), 256, SMB_QO>>>(x, gamma, beta, bo, Wlin);
    k_epi<<<Bn, Pn>>>(gamma, beta, blin, Wp, bp, out);
}

// round 13
// speedup vs baseline: 1.4850x; 1.1017x over previous
#include <cuda_runtime.h>
#include <cstdint>

#define Bn 32
#define Fn 64
#define Ln 8192
#define Pn 96
#define SR 132    // data tile row stride (floats)

typedef unsigned long long ull;

// ---------------- scratch (device globals) ----------------
__device__ float g_mean[Bn * Fn];
__device__ float g_istd[Bn * Fn];
__device__ float g_stdp[Bn * Fn];
__device__ float g_KV[Bn * 512];
__device__ float g_Z[Bn * 64];
__device__ float g_M[Bn * Pn * Fn];
// pre-folded plain-float weights, layout [k(=input dim)][e(=output dim)]
__device__ float g_Wqf[4096], g_Wkf[4096], g_Wvf[4096], g_Wof[4096];
__device__ float g_dq[64], g_cq[64], g_dk[64], g_ck[64], g_dv[64], g_cv[64];

// ---------------- helpers ----------------
__device__ __forceinline__ void fma2(ull& d, ull a, ull b) {
    asm("fma.rn.f32x2 %0, %1, %2, %0;" : "+l"(d) : "l"(a), "l"(b));
}
__device__ __forceinline__ float2 upk(ull v) {
    float2 r;
    asm("mov.b64 {%0, %1}, %2;" : "=f"(r.x), "=f"(r.y) : "l"(v));
    return r;
}
__device__ __forceinline__ ull pk2(float a, float b) {
    ull r;
    asm("mov.b64 %0, {%1, %2};" : "=l"(r) : "f"(a), "f"(b));
    return r;
}
__device__ __forceinline__ ull dup(float a) { return pk2(a, a); }
__device__ __forceinline__ float phi_fn(float v) {
    return v > 0.f ? v + 1.f : __expf(v);   // elu(x)+1
}
__device__ __forceinline__ unsigned tf32r(float x) {
    unsigned u;
    asm("cvt.rna.tf32.f32 %0, %1;" : "=r"(u) : "f"(x));
    return u;
}
__device__ __forceinline__ void mma_tf32(float c[4], const unsigned a[4], const unsigned b[2]) {
    asm volatile(
        "mma.sync.aligned.m16n8k8.row.col.f32.tf32.tf32.f32 "
        "{%0,%1,%2,%3}, {%4,%5,%6,%7}, {%8,%9}, {%0,%1,%2,%3};"
        : "+f"(c[0]), "+f"(c[1]), "+f"(c[2]), "+f"(c[3])
        : "r"(a[0]), "r"(a[1]), "r"(a[2]), "r"(a[3]), "r"(b[0]), "r"(b[1]));
}

// ---------------- prep (block 0) + zero accumulators (blocks 1..32) ----------------
__global__ void __launch_bounds__(256) k_prep(
    const float* __restrict__ lnw, const float* __restrict__ lnb,
    const float* __restrict__ Wq, const float* __restrict__ bq,
    const float* __restrict__ Wk, const float* __restrict__ bk,
    const float* __restrict__ Wv, const float* __restrict__ bv,
    const float* __restrict__ Wo)
{
    if (blockIdx.x > 0) {
        int zb = blockIdx.x - 1;
        int base = zb * 6144;
        for (int i = threadIdx.x; i < 6144; i += 256) g_M[base + i] = 0.f;
        if (zb < 16) {
            for (int i = threadIdx.x; i < 1024; i += 256) g_KV[zb * 1024 + i] = 0.f;
        } else {
            int zz = zb - 16;
            for (int i = threadIdx.x; i < 128; i += 256) g_Z[zz * 128 + i] = 0.f;
        }
        return;
    }
    int tid = threadIdx.x;
#pragma unroll
    for (int i = 0; i < 16; i++) {
        int idx = tid + i * 256;          // idx = f*64 + e
        int f = idx >> 6, e = idx & 63;
        float lw = lnw[f];
        g_Wqf[idx] = Wq[e * 64 + f] * lw;
        g_Wkf[idx] = Wk[e * 64 + f] * lw;
        g_Wvf[idx] = Wv[e * 64 + f] * lw;
        g_Wof[idx] = Wo[e * 64 + f];      // WoT[k=e_att][fo]
    }
    if (tid < 64) {
        int e = tid;
        float dq = 0.f, cq = 0.f, dk = 0.f, ck = 0.f, dv = 0.f, cv = 0.f;
        for (int f = 0; f < 64; f++) {
            float lw = lnw[f], lb2 = lnb[f];
            float wq = Wq[e * 64 + f], wk = Wk[e * 64 + f], wv = Wv[e * 64 + f];
            dq += wq * lw;  cq = fmaf(lb2, wq, cq);
            dk += wk * lw;  ck = fmaf(lb2, wk, ck);
            dv += wv * lw;  cv = fmaf(lb2, wv, cv);
        }
        g_dq[e] = dq; g_cq[e] = cq + bq[e];
        g_dk[e] = dk; g_ck[e] = ck + bk[e];
        g_dv[e] = dv; g_cv[e] = cv + bv[e];
    }
}

// ---------------- RevIN stats per (b,f) ----------------
__global__ void __launch_bounds__(256) k_stats(const float* __restrict__ x) {
    int bf = blockIdx.x;
    const float4* p = (const float4*)(x + (size_t)bf * Ln);
    float s1 = 0.f, s2 = 0.f;
    for (int i = threadIdx.x; i < Ln / 4; i += 256) {
        float4 v = p[i];
        s1 += (v.x + v.y) + (v.z + v.w);
        s2 = fmaf(v.x, v.x, s2); s2 = fmaf(v.y, v.y, s2);
        s2 = fmaf(v.z, v.z, s2); s2 = fmaf(v.w, v.w, s2);
    }
    __shared__ float r1[256], r2[256];
    r1[threadIdx.x] = s1; r2[threadIdx.x] = s2;
    __syncthreads();
    for (int s = 128; s > 0; s >>= 1) {
        if (threadIdx.x < s) {
            r1[threadIdx.x] += r1[threadIdx.x + s];
            r2[threadIdx.x] += r2[threadIdx.x + s];
        }
        __syncthreads();
    }
    if (threadIdx.x == 0) {
        float S1 = r1[0], S2 = r2[0];
        float mean = S1 / (float)Ln;
        float var = (S2 - S1 * mean) / (float)(Ln - 1);
        var = fmaxf(var, 0.f);
        float stdp = sqrtf(var) + 1e-5f;
        g_mean[bf] = mean; g_stdp[bf] = stdp; g_istd[bf] = 1.f / stdp;
    }
}

// ---------------- kernel 2: fused K+V projections + KV,Z (256 threads, 4e x 8l) ----------------
__global__ void __launch_bounds__(256, 2) k_kv(
    const float* __restrict__ x, const float* __restrict__ gamma, const float* __restrict__ beta)
{
    extern __shared__ float sm[];
    float* xns = sm;                     // 64*SR; later phi(K)
    float* vb  = sm + 64 * SR;           // 64*SR
    float* wv  = sm + 2 * 64 * SR;       // 4096 floats
    float* wk  = wv + 4096;              // 4096 floats
    __shared__ float mus[128], rss[128], As[64], Cs[64];
    __shared__ float dks[64], cks[64], dvs[64], cvs[64];

    int b = blockIdx.y, tid = threadIdx.x;
    int l0b = blockIdx.x * 128;

    if (tid < 64) {
        float a = gamma[tid] * g_istd[b * 64 + tid];
        As[tid] = a;
        Cs[tid] = beta[tid] - g_mean[b * 64 + tid] * a;
        dks[tid] = g_dk[tid]; cks[tid] = g_ck[tid];
        dvs[tid] = g_dv[tid]; cvs[tid] = g_cv[tid];
    }
#pragma unroll
    for (int i = 0; i < 4; i++) {
        ((float4*)wv)[tid + i * 256] = ((const float4*)g_Wvf)[tid + i * 256];
        ((float4*)wk)[tid + i * 256] = ((const float4*)g_Wkf)[tid + i * 256];
    }
    __syncthreads();
#pragma unroll
    for (int i = 0; i < 8; i++) {
        int idx = tid + i * 256;
        int f = idx >> 5, c = idx & 31;
        float4 v = *(const float4*)(x + ((size_t)(b * 64 + f)) * Ln + l0b + c * 4);
        float a = As[f], c0 = Cs[f];
        v.x = fmaf(v.x, a, c0); v.y = fmaf(v.y, a, c0);
        v.z = fmaf(v.z, a, c0); v.w = fmaf(v.w, a, c0);
        *(float4*)(xns + f * SR + c * 4) = v;
    }
    __syncthreads();
    if (tid < 128) {
        float s1 = 0.f, s2 = 0.f;
#pragma unroll
        for (int f = 0; f < 64; f++) { float t = xns[f * SR + tid]; s1 += t; s2 = fmaf(t, t, s2); }
        float mu = s1 * (1.f / 64.f);
        mus[tid] = mu;
        rss[tid] = rsqrtf(fmaf(-mu, mu, s2 * (1.f / 64.f)) + 1e-5f);
    }
    __syncthreads();

    int lg = tid & 15, eg = tid >> 4;
    int e0 = eg * 4;
    const float* hb = xns + 2 * lg;
    const float* wvp = wv + e0;
    const float* wkp = wk + e0;

    ull aV[4][4], aK[4][4];
#pragma unroll
    for (int i = 0; i < 4; i++)
#pragma unroll
        for (int p = 0; p < 4; p++) { aV[i][p] = 0ULL; aK[i][p] = 0ULL; }

#pragma unroll 4
    for (int k = 0; k < 64; k++) {
        ull h[4];
        h[0] = *(const ull*)(hb + k * SR);
        h[1] = *(const ull*)(hb + k * SR + 32);
        h[2] = *(const ull*)(hb + k * SR + 64);
        h[3] = *(const ull*)(hb + k * SR + 96);
        float4 v4 = *(const float4*)(wvp + k * 64);
        float4 k4 = *(const float4*)(wkp + k * 64);
        ull wvd[4] = {dup(v4.x), dup(v4.y), dup(v4.z), dup(v4.w)};
        ull wkd[4] = {dup(k4.x), dup(k4.y), dup(k4.z), dup(k4.w)};
#pragma unroll
        for (int i = 0; i < 4; i++)
#pragma unroll
            for (int p = 0; p < 4; p++) {
                fma2(aV[i][p], wvd[i], h[p]);
                fma2(aK[i][p], wkd[i], h[p]);
            }
    }

    float2 muv[4], rsv[4];
#pragma unroll
    for (int p = 0; p < 4; p++) {
        muv[p] = upk(*(const ull*)(mus + 2 * lg + 32 * p));
        rsv[p] = upk(*(const ull*)(rss + 2 * lg + 32 * p));
    }

#pragma unroll
    for (int i = 0; i < 4; i++) {
        int e = e0 + i; float dv = dvs[e], cv = cvs[e];
#pragma unroll
        for (int p = 0; p < 4; p++) {
            float2 s = upk(aV[i][p]);
            *(ull*)(vb + e * SR + 2 * lg + 32 * p) =
                pk2(fmaf(rsv[p].x, s.x - muv[p].x * dv, cv),
                    fmaf(rsv[p].y, s.y - muv[p].y * dv, cv));
        }
    }
    ull kw[4][4];
#pragma unroll
    for (int i = 0; i < 4; i++) {
        int e = e0 + i; float dk = dks[e], ck = cks[e];
#pragma unroll
        for (int p = 0; p < 4; p++) {
            float2 s = upk(aK[i][p]);
            kw[i][p] = pk2(phi_fn(fmaf(rsv[p].x, s.x - muv[p].x * dk, ck)),
                           phi_fn(fmaf(rsv[p].y, s.y - muv[p].y * dk, ck)));
        }
    }
    __syncthreads();   // all GEMM reads of xns done
#pragma unroll
    for (int i = 0; i < 4; i++)
#pragma unroll
        for (int p = 0; p < 4; p++)
            *(ull*)(xns + (e0 + i) * SR + 2 * lg + 32 * p) = kw[i][p];
    __syncthreads();

    // ---- KV accumulation: two (hh,d,e) entries per thread ----
    {
        int hh = tid >> 5;
        int rem = tid & 31;
        int d  = rem >> 2;
        int e2 = (rem & 3) * 2;
        const float* kr  = xns + (hh * 8 + d) * SR;
        const float* vr0 = vb + (hh * 8 + e2) * SR;
        const float* vr1 = vr0 + SR;
        ull a0 = 0ULL, a1 = 0ULL;
#pragma unroll 8
        for (int j = 0; j < 128; j += 4) {
            ulonglong2 kk = *(const ulonglong2*)(kr + j);
            ulonglong2 v0 = *(const ulonglong2*)(vr0 + j);
            ulonglong2 v1 = *(const ulonglong2*)(vr1 + j);
            fma2(a0, kk.x, v0.x); fma2(a0, kk.y, v0.y);
            fma2(a1, kk.x, v1.x); fma2(a1, kk.y, v1.y);
        }
        float2 t0 = upk(a0), t1 = upk(a1);
        atomicAdd(&g_KV[(b * 8 + hh) * 64 + d * 8 + e2],     t0.x + t0.y);
        atomicAdd(&g_KV[(b * 8 + hh) * 64 + d * 8 + e2 + 1], t1.x + t1.y);
    }
    if (tid < 64) {
        const float* kr = xns + tid * SR;
        float s = 0.f;
#pragma unroll
        for (int j = 0; j < 128; j += 4) {
            float4 v = *(const float4*)(kr + j);
            s += (v.x + v.y) + (v.z + v.w);
        }
        atomicAdd(&g_Z[b * 64 + tid], s);
    }
}

// ---------------- kernel 3: Q, attention, Wo+residual, tf32-mma temporal (256 threads) ----------------
__global__ void __launch_bounds__(256, 2) k_qo(
    const float* __restrict__ x, const float* __restrict__ gamma, const float* __restrict__ beta,
    const float* __restrict__ bo, const float* __restrict__ Wlin)
{
    extern __shared__ float sm[];
    float* wq  = sm;                    // 4096 floats (Wq, then WoT)
    float* xns = sm + 4224;             // 64*SR (8448)
    float* qb  = sm + 12672;            // 64*SR; later y tile (tf32, stride 132)
    float* wls = sm;                    // Wlin slab (tf32): 96 rows x 132 = 12672 over wq+gap+xns
    __shared__ float mus[128], rss[128], As[64], Cs[64], dqs[64], cqs[64], bos[64];
    __shared__ __align__(16) float KVs[512];
    __shared__ float Zs[64];

    int b = blockIdx.y, tid = threadIdx.x;
    int l0b = blockIdx.x * 128;

    if (tid < 64) {
        float a = gamma[tid] * g_istd[b * 64 + tid];
        As[tid] = a;
        Cs[tid] = beta[tid] - g_mean[b * 64 + tid] * a;
        dqs[tid] = g_dq[tid]; cqs[tid] = g_cq[tid];
        bos[tid] = bo[tid];
        Zs[tid] = g_Z[b * 64 + tid];
    }
    KVs[tid] = g_KV[b * 512 + tid];
    KVs[tid + 256] = g_KV[b * 512 + 256 + tid];
#pragma unroll
    for (int i = 0; i < 4; i++)
        ((float4*)wq)[tid + i * 256] = ((const float4*)g_Wqf)[tid + i * 256];
    __syncthreads();
#pragma unroll
    for (int i = 0; i < 8; i++) {
        int idx = tid + i * 256;
        int f = idx >> 5, c = idx & 31;
        float4 v = *(const float4*)(x + ((size_t)(b * 64 + f)) * Ln + l0b + c * 4);
        float a = As[f], c0 = Cs[f];
        v.x = fmaf(v.x, a, c0); v.y = fmaf(v.y, a, c0);
        v.z = fmaf(v.z, a, c0); v.w = fmaf(v.w, a, c0);
        *(float4*)(xns + f * SR + c * 4) = v;
    }
    __syncthreads();
    if (tid < 128) {
        float s1 = 0.f, s2 = 0.f;
#pragma unroll
        for (int f = 0; f < 64; f++) { float t = xns[f * SR + tid]; s1 += t; s2 = fmaf(t, t, s2); }
        float mu = s1 * (1.f / 64.f);
        mus[tid] = mu;
        rss[tid] = rsqrtf(fmaf(-mu, mu, s2 * (1.f / 64.f)) + 1e-5f);
    }
    __syncthreads();

    int lg = tid & 15, eg = tid >> 4;
    int e0 = eg * 4;
    const float* wqp = wq + e0;

    float2 muv[4], rsv[4];
#pragma unroll
    for (int p = 0; p < 4; p++) {
        muv[p] = upk(*(const ull*)(mus + 2 * lg + 32 * p));
        rsv[p] = upk(*(const ull*)(rss + 2 * lg + 32 * p));
    }

    // ---- Q GEMM (4e x 8l) -> phi -> qb ----
    {
        const float* hb = xns + 2 * lg;
        ull a[4][4];
#pragma unroll
        for (int i = 0; i < 4; i++)
#pragma unroll
            for (int p = 0; p < 4; p++) a[i][p] = 0ULL;
#pragma unroll 4
        for (int k = 0; k < 64; k++) {
            ull h[4];
            h[0] = *(const ull*)(hb + k * SR);
            h[1] = *(const ull*)(hb + k * SR + 32);
            h[2] = *(const ull*)(hb + k * SR + 64);
            h[3] = *(const ull*)(hb + k * SR + 96);
            float4 w4 = *(const float4*)(wqp + k * 64);
            ull wd[4] = {dup(w4.x), dup(w4.y), dup(w4.z), dup(w4.w)};
#pragma unroll
            for (int i = 0; i < 4; i++)
#pragma unroll
                for (int p = 0; p < 4; p++) fma2(a[i][p], wd[i], h[p]);
        }
#pragma unroll
        for (int i = 0; i < 4; i++) {
            int e = e0 + i; float dq = dqs[e], cq = cqs[e];
#pragma unroll
            for (int p = 0; p < 4; p++) {
                float2 s = upk(a[i][p]);
                *(ull*)(qb + e * SR + 2 * lg + 32 * p) =
                    pk2(phi_fn(fmaf(rsv[p].x, s.x - muv[p].x * dq, cq)),
                        phi_fn(fmaf(rsv[p].y, s.y - muv[p].y * dq, cq)));
            }
        }
    }
    __syncthreads();   // q complete; Wq reads done

    // ---- reload w <- WoT; attention (4 heads per thread, vectorized KV) ----
#pragma unroll
    for (int i = 0; i < 4; i++)
        ((float4*)wq)[tid + i * 256] = ((const float4*)g_Wof)[tid + i * 256];
    {
        int la = tid & 127;
        int hgrp = tid >> 7;   // 0..1
#pragma unroll
        for (int t = 0; t < 4; t++) {
            int hh = hgrp * 4 + t;
            float q[8];
#pragma unroll
            for (int d = 0; d < 8; d++) q[d] = qb[(hh * 8 + d) * SR + la];
            float nrm = 1e-6f;
#pragma unroll
            for (int d = 0; d < 8; d++) nrm = fmaf(q[d], Zs[hh * 8 + d], nrm);
            float inv = 1.f / nrm;
            float s[8] = {0.f, 0.f, 0.f, 0.f, 0.f, 0.f, 0.f, 0.f};
#pragma unroll
            for (int d = 0; d < 8; d++) {
                float4 kv0 = *(const float4*)(KVs + hh * 64 + d * 8);
                float4 kv1 = *(const float4*)(KVs + hh * 64 + d * 8 + 4);
                float qd = q[d];
                s[0] = fmaf(qd, kv0.x, s[0]); s[1] = fmaf(qd, kv0.y, s[1]);
                s[2] = fmaf(qd, kv0.z, s[2]); s[3] = fmaf(qd, kv0.w, s[3]);
                s[4] = fmaf(qd, kv1.x, s[4]); s[5] = fmaf(qd, kv1.y, s[5]);
                s[6] = fmaf(qd, kv1.z, s[6]); s[7] = fmaf(qd, kv1.w, s[7]);
            }
#pragma unroll
            for (int j = 0; j < 8; j++)
                qb[(hh * 8 + j) * SR + la] = s[j] * inv;
        }
    }
    __syncthreads();

    // ---- Wo GEMM + bias + residual -> y (tf32, stride 132, same qb region) ----
    {
        const float* hb = qb + 2 * lg;
        ull a[4][4];
#pragma unroll
        for (int i = 0; i < 4; i++)
#pragma unroll
            for (int p = 0; p < 4; p++) a[i][p] = 0ULL;
#pragma unroll 4
        for (int k = 0; k < 64; k++) {
            ull h[4];
            h[0] = *(const ull*)(hb + k * SR);
            h[1] = *(const ull*)(hb + k * SR + 32);
            h[2] = *(const ull*)(hb + k * SR + 64);
            h[3] = *(const ull*)(hb + k * SR + 96);
            float4 w4 = *(const float4*)(wqp + k * 64);
            ull wd[4] = {dup(w4.x), dup(w4.y), dup(w4.z), dup(w4.w)};
#pragma unroll
            for (int i = 0; i < 4; i++)
#pragma unroll
                for (int p = 0; p < 4; p++) fma2(a[i][p], wd[i], h[p]);
        }
        ull yo[4][4];
#pragma unroll
        for (int i = 0; i < 4; i++) {
            int fo = e0 + i;
            float bb = bos[fo];
#pragma unroll
            for (int p = 0; p < 4; p++) {
                float2 r = upk(*(const ull*)(xns + fo * SR + 2 * lg + 32 * p));
                float2 s = upk(a[i][p]);
                // convert to tf32 bit-patterns for the mma temporal
                unsigned u0 = tf32r(s.x + bb + r.x);
                unsigned u1 = tf32r(s.y + bb + r.y);
                yo[i][p] = pk2(__uint_as_float(u0), __uint_as_float(u1));
            }
        }
        __syncthreads();   // Wo GEMM qb-reads + residual xns-reads done
#pragma unroll
        for (int i = 0; i < 4; i++)
#pragma unroll
            for (int p = 0; p < 4; p++)
                *(ull*)(qb + (e0 + i) * SR + 2 * lg + 32 * p) = yo[i][p];
    }
    // ---- Wlin slab (tf32, 96 x 132-stride) into wq+xns region ----
#pragma unroll
    for (int i = 0; i < 12; i++) {
        int idx = tid + i * 256;               // 3072 float4 = 96 rows x 32
        int p = idx >> 5, c4 = idx & 31;
        float4 v = *(const float4*)(Wlin + (size_t)p * Ln + l0b + c4 * 4);
        v.x = __uint_as_float(tf32r(v.x));
        v.y = __uint_as_float(tf32r(v.y));
        v.z = __uint_as_float(tf32r(v.z));
        v.w = __uint_as_float(tf32r(v.w));
        *(float4*)(wls + p * 132 + c4 * 4) = v;
    }
    __syncthreads();

    // ---- temporal GEMM via mma.sync m16n8k8 tf32 ----
    // M = p (96 = 6x16), N = f (64 = 8x8), K = l (128 = 16x8)
    // A = Wlin[p][l] row-major (stride 132), B = y[f][l] "col-major" (stride 132)
    {
        int lane = tid & 31, w = tid >> 5;
        int gid = lane >> 2, tig = lane & 3;
        int mtg = w & 1, ntg = w >> 1;          // warp: 3 m-tiles x 2 n-tiles
        float c[3][2][4];
#pragma unroll
        for (int mi = 0; mi < 3; mi++)
#pragma unroll
            for (int ni = 0; ni < 2; ni++)
#pragma unroll
                for (int q = 0; q < 4; q++) c[mi][ni][q] = 0.f;

#pragma unroll
        for (int kt = 0; kt < 16; kt++) {
            int lcol = kt * 8 + tig;
            unsigned a[3][4], bf[2][2];
#pragma unroll
            for (int mi = 0; mi < 3; mi++) {
                const float* ab = wls + (mtg * 48 + mi * 16 + gid) * 132 + lcol;
                a[mi][0] = __float_as_uint(ab[0]);
                a[mi][1] = __float_as_uint(ab[8 * 132]);
                a[mi][2] = __float_as_uint(ab[4]);
                a[mi][3] = __float_as_uint(ab[8 * 132 + 4]);
            }
#pragma unroll
            for (int ni = 0; ni < 2; ni++) {
                const float* bb = qb + (ntg * 16 + ni * 8 + gid) * 132 + lcol;
                bf[ni][0] = __float_as_uint(bb[0]);
                bf[ni][1] = __float_as_uint(bb[4]);
            }
#pragma unroll
            for (int mi = 0; mi < 3; mi++)
#pragma unroll
                for (int ni = 0; ni < 2; ni++)
                    mma_tf32(c[mi][ni], a[mi], bf[ni]);
        }
#pragma unroll
        for (int mi = 0; mi < 3; mi++) {
            int p0 = mtg * 48 + mi * 16 + gid;
#pragma unroll
            for (int ni = 0; ni < 2; ni++) {
                int f0 = ntg * 16 + ni * 8 + 2 * tig;
                float* mb = &g_M[(b * 96 + p0) * 64 + f0];
                atomicAdd(mb,            c[mi][ni][0]);
                atomicAdd(mb + 1,        c[mi][ni][1]);
                atomicAdd(mb + 8 * 64,     c[mi][ni][2]);
                atomicAdd(mb + 8 * 64 + 1, c[mi][ni][3]);
            }
        }
    }
}

// ---------------- kernel 5: denorm + projector ----------------
__global__ void k_epi(const float* __restrict__ gamma, const float* __restrict__ beta,
                      const float* __restrict__ blin, const float* __restrict__ Wp,
                      const float* __restrict__ bp, float* __restrict__ out) {
    int b = blockIdx.x, p = threadIdx.x;
    float bl = blin[p];
    float s = bp[0];
#pragma unroll
    for (int f = 0; f < 64; f++) {
        float y = g_M[(b * 96 + p) * 64 + f] + bl;
        y = (y - beta[f]) / gamma[f];
        y = fmaf(y, g_stdp[b * 64 + f], g_mean[b * 64 + f]);
        s = fmaf(y, Wp[f], s);
    }
    out[b * 96 + p] = s;
}

// ---------------- launch ----------------
extern "C" void kernel_launch(void* const* d_in, const int* in_sizes, int n_in,
                              void* d_out, int out_size) {
    (void)in_sizes; (void)n_in; (void)out_size;
    const float* x     = (const float*)d_in[0];
    const float* gamma = (const float*)d_in[1];
    const float* beta  = (const float*)d_in[2];
    const float* lnw   = (const float*)d_in[3];
    const float* lnb   = (const float*)d_in[4];
    const float* Wq    = (const float*)d_in[5];
    const float* bq    = (const float*)d_in[6];
    const float* Wk    = (const float*)d_in[7];
    const float* bk    = (const float*)d_in[8];
    const float* Wv    = (const float*)d_in[9];
    const float* bv    = (const float*)d_in[10];
    const float* Wo    = (const float*)d_in[11];
    const float* bo    = (const float*)d_in[12];
    const float* Wlin  = (const float*)d_in[13];
    const float* blin  = (const float*)d_in[14];
    const float* Wp    = (const float*)d_in[15];
    const float* bp    = (const float*)d_in[16];
    float* out = (float*)d_out;

    const int SMB_KV = (2 * 64 * SR + 8192) * 4;   // 100352 B
    const int SMB_QO = (12672 + 64 * SR) * 4;      // 84480 B
    cudaFuncSetAttribute(k_kv, cudaFuncAttributeMaxDynamicSharedMemorySize, SMB_KV);
    cudaFuncSetAttribute(k_qo, cudaFuncAttributeMaxDynamicSharedMemorySize, SMB_QO);

    k_prep<<<33, 256>>>(lnw, lnb, Wq, bq, Wk, bk, Wv, bv, Wo);
    k_stats<<<Bn * Fn, 256>>>(x);
    k_kv<<<dim3(Ln / 128, Bn), 256, SMB_KV>>>(x, gamma, beta);
    k_qo<<<dim3(Ln / 128, Bn), 256, SMB_QO>>>(x, gamma, beta, bo, Wlin);
    k_epi<<<Bn, Pn>>>(gamma, beta, blin, Wp, bp, out);
}

// round 15
// speedup vs baseline: 1.7200x; 1.1582x over previous
#include <cuda_runtime.h>
#include <cstdint>

#define Bn 32
#define Fn 64
#define Ln 8192
#define Pn 96
#define SR 132    // data tile row stride (floats)

typedef unsigned long long ull;

// ---------------- scratch (device globals) ----------------
__device__ float g_mean[Bn * Fn];
__device__ float g_istd[Bn * Fn];
__device__ float g_stdp[Bn * Fn];
__device__ float g_KV[Bn * 512];
__device__ float g_Z[Bn * 64];
__device__ float g_M[Bn * Pn * Fn];
// weights: [f][e] folded (for k_qo f32x2 path) and [e][f] folded (for k_kv mma path)
__device__ float g_Wqf[4096], g_Wof[4096];
__device__ float g_WkA[4096], g_WvA[4096];   // [e][f] * lnw[f], tf32-rounded
__device__ float g_dq[64], g_cq[64], g_dk[64], g_ck[64], g_dv[64], g_cv[64];

// ---------------- helpers ----------------
__device__ __forceinline__ void fma2(ull& d, ull a, ull b) {
    asm("fma.rn.f32x2 %0, %1, %2, %0;" : "+l"(d) : "l"(a), "l"(b));
}
__device__ __forceinline__ float2 upk(ull v) {
    float2 r;
    asm("mov.b64 {%0, %1}, %2;" : "=f"(r.x), "=f"(r.y) : "l"(v));
    return r;
}
__device__ __forceinline__ ull pk2(float a, float b) {
    ull r;
    asm("mov.b64 %0, {%1, %2};" : "=l"(r) : "f"(a), "f"(b));
    return r;
}
__device__ __forceinline__ ull dup(float a) { return pk2(a, a); }
__device__ __forceinline__ float phi_fn(float v) {
    return v > 0.f ? v + 1.f : __expf(v);   // elu(x)+1
}
__device__ __forceinline__ unsigned tf32r(float x) {
    unsigned u;
    asm("cvt.rna.tf32.f32 %0, %1;" : "=r"(u) : "f"(x));
    return u;
}
__device__ __forceinline__ void mma_tf32(float c[4], const unsigned a[4], const unsigned b[2]) {
    asm volatile(
        "mma.sync.aligned.m16n8k8.row.col.f32.tf32.tf32.f32 "
        "{%0,%1,%2,%3}, {%4,%5,%6,%7}, {%8,%9}, {%0,%1,%2,%3};"
        : "+f"(c[0]), "+f"(c[1]), "+f"(c[2]), "+f"(c[3])
        : "r"(a[0]), "r"(a[1]), "r"(a[2]), "r"(a[3]), "r"(b[0]), "r"(b[1]));
}

// ---------------- prep (block 0) + zero accumulators (blocks 1..32) ----------------
__global__ void __launch_bounds__(256) k_prep(
    const float* __restrict__ lnw, const float* __restrict__ lnb,
    const float* __restrict__ Wq, const float* __restrict__ bq,
    const float* __restrict__ Wk, const float* __restrict__ bk,
    const float* __restrict__ Wv, const float* __restrict__ bv,
    const float* __restrict__ Wo)
{
    if (blockIdx.x > 0) {
        int zb = blockIdx.x - 1;
        int base = zb * 6144;
        for (int i = threadIdx.x; i < 6144; i += 256) g_M[base + i] = 0.f;
        if (zb < 16) {
            for (int i = threadIdx.x; i < 1024; i += 256) g_KV[zb * 1024 + i] = 0.f;
        } else {
            int zz = zb - 16;
            for (int i = threadIdx.x; i < 128; i += 256) g_Z[zz * 128 + i] = 0.f;
        }
        return;
    }
    int tid = threadIdx.x;
#pragma unroll
    for (int i = 0; i < 16; i++) {
        int idx = tid + i * 256;
        {   // [f][e] layouts for k_qo
            int f = idx >> 6, e = idx & 63;
            g_Wqf[idx] = Wq[e * 64 + f] * lnw[f];
            g_Wof[idx] = Wo[e * 64 + f];      // WoT[k=e_att][fo]
        }
        {   // [e][f] layouts (direct) for k_kv mma, tf32-rounded
            int f = idx & 63;
            g_WkA[idx] = __uint_as_float(tf32r(Wk[idx] * lnw[f]));
            g_WvA[idx] = __uint_as_float(tf32r(Wv[idx] * lnw[f]));
        }
    }
    if (tid < 64) {
        int e = tid;
        float dq = 0.f, cq = 0.f, dk = 0.f, ck = 0.f, dv = 0.f, cv = 0.f;
        for (int f = 0; f < 64; f++) {
            float lw = lnw[f], lb2 = lnb[f];
            float wq = Wq[e * 64 + f], wk = Wk[e * 64 + f], wv = Wv[e * 64 + f];
            dq += wq * lw;  cq = fmaf(lb2, wq, cq);
            dk += wk * lw;  ck = fmaf(lb2, wk, ck);
            dv += wv * lw;  cv = fmaf(lb2, wv, cv);
        }
        g_dq[e] = dq; g_cq[e] = cq + bq[e];
        g_dk[e] = dk; g_ck[e] = ck + bk[e];
        g_dv[e] = dv; g_cv[e] = cv + bv[e];
    }
}

// ---------------- RevIN stats per (b,f) ----------------
__global__ void __launch_bounds__(256) k_stats(const float* __restrict__ x) {
    int bf = blockIdx.x;
    const float4* p = (const float4*)(x + (size_t)bf * Ln);
    float s1 = 0.f, s2 = 0.f;
    for (int i = threadIdx.x; i < Ln / 4; i += 256) {
        float4 v = p[i];
        s1 += (v.x + v.y) + (v.z + v.w);
        s2 = fmaf(v.x, v.x, s2); s2 = fmaf(v.y, v.y, s2);
        s2 = fmaf(v.z, v.z, s2); s2 = fmaf(v.w, v.w, s2);
    }
    __shared__ float r1[256], r2[256];
    r1[threadIdx.x] = s1; r2[threadIdx.x] = s2;
    __syncthreads();
    for (int s = 128; s > 0; s >>= 1) {
        if (threadIdx.x < s) {
            r1[threadIdx.x] += r1[threadIdx.x + s];
            r2[threadIdx.x] += r2[threadIdx.x + s];
        }
        __syncthreads();
    }
    if (threadIdx.x == 0) {
        float S1 = r1[0], S2 = r2[0];
        float mean = S1 / (float)Ln;
        float var = (S2 - S1 * mean) / (float)(Ln - 1);
        var = fmaxf(var, 0.f);
        float stdp = sqrtf(var) + 1e-5f;
        g_mean[bf] = mean; g_stdp[bf] = stdp; g_istd[bf] = 1.f / stdp;
    }
}

// ---------------- kernel 2: K/V via tf32 mma + KV,Z (256 threads) ----------------
__global__ void __launch_bounds__(256, 2) k_kv(
    const float* __restrict__ x, const float* __restrict__ gamma, const float* __restrict__ beta)
{
    extern __shared__ float sm[];
    float* xfl = sm;                 // [f][l] s132 (8448); later vb [e][l] s132
    float* xnT = sm + 8448;          // [l][f] s68  (8704); later kb [e][l] s132 (8448)
    float* wkA = sm + 8448 + 8704;   // [e][f] s68 (4352)
    float* wvA = wkA + 4352;         // 4352
    __shared__ float mus[128], rss[128], As[64], Cs[64];
    __shared__ float dks[64], cks[64], dvs[64], cvs[64];

    int b = blockIdx.y, tid = threadIdx.x;
    int l0b = blockIdx.x * 128;

    if (tid < 64) {
        float a = gamma[tid] * g_istd[b * 64 + tid];
        As[tid] = a;
        Cs[tid] = beta[tid] - g_mean[b * 64 + tid] * a;
        dks[tid] = g_dk[tid]; cks[tid] = g_ck[tid];
        dvs[tid] = g_dv[tid]; cvs[tid] = g_cv[tid];
    }
    // stage A-weights [e][f] at stride 68 (already tf32-rounded in prep)
#pragma unroll
    for (int i = 0; i < 4; i++) {
        int idx = tid + i * 256;             // 1024 float4s
        int e = idx >> 4, c = (idx & 15) * 4;
        *(float4*)(wkA + e * 68 + c) = ((const float4*)g_WkA)[idx];
        *(float4*)(wvA + e * 68 + c) = ((const float4*)g_WvA)[idx];
    }
    __syncthreads();   // As/Cs visible to ALL threads before xn staging (R14 bug fix)
    // stage xn [f][l]
#pragma unroll
    for (int i = 0; i < 8; i++) {
        int idx = tid + i * 256;
        int f = idx >> 5, c = idx & 31;
        float4 v = *(const float4*)(x + ((size_t)(b * 64 + f)) * Ln + l0b + c * 4);
        float a = As[f], c0 = Cs[f];
        v.x = fmaf(v.x, a, c0); v.y = fmaf(v.y, a, c0);
        v.z = fmaf(v.z, a, c0); v.w = fmaf(v.w, a, c0);
        *(float4*)(xfl + f * SR + c * 4) = v;
    }
    __syncthreads();
    // LN stats (from exact fp32 xn, conflict-free column reads)
    if (tid < 128) {
        float s1 = 0.f, s2 = 0.f;
#pragma unroll
        for (int f = 0; f < 64; f++) { float t = xfl[f * SR + tid]; s1 += t; s2 = fmaf(t, t, s2); }
        float mu = s1 * (1.f / 64.f);
        mus[tid] = mu;
        rss[tid] = rsqrtf(fmaf(-mu, mu, s2 * (1.f / 64.f)) + 1e-5f);
    }
    // transpose to xnT[l][f] (tf32-rounded): thread = (l = tid&127, fgrp = tid>>7)
    {
        int l = tid & 127, fgrp = tid >> 7;
        float tv[32];
#pragma unroll
        for (int i = 0; i < 32; i++)
            tv[i] = __uint_as_float(tf32r(xfl[(fgrp * 32 + i) * SR + l]));
#pragma unroll
        for (int j = 0; j < 8; j++)
            *(float4*)(xnT + l * 68 + fgrp * 32 + j * 4) =
                make_float4(tv[4 * j], tv[4 * j + 1], tv[4 * j + 2], tv[4 * j + 3]);
    }
    __syncthreads();

    // ---- K & V GEMMs via mma: M=e(64: 2x2 tiles), N=l(128: 4x4 tiles), K=f(64: 8 k-tiles)
    int lane = tid & 31, w = tid >> 5;
    int gid = lane >> 2, tig = lane & 3;
    int mtg = w & 1, ntg = w >> 1;
    float aK[2][4][4], aV[2][4][4];
#pragma unroll
    for (int mi = 0; mi < 2; mi++)
#pragma unroll
        for (int ni = 0; ni < 4; ni++)
#pragma unroll
            for (int q = 0; q < 4; q++) { aK[mi][ni][q] = 0.f; aV[mi][ni][q] = 0.f; }

#pragma unroll
    for (int kt = 0; kt < 8; kt++) {
        unsigned Ak[2][4], Av[2][4], Bf[4][2];
#pragma unroll
        for (int mi = 0; mi < 2; mi++) {
            const float* ak = wkA + (mtg * 32 + mi * 16 + gid) * 68 + kt * 8 + tig;
            Ak[mi][0] = __float_as_uint(ak[0]);
            Ak[mi][1] = __float_as_uint(ak[8 * 68]);
            Ak[mi][2] = __float_as_uint(ak[4]);
            Ak[mi][3] = __float_as_uint(ak[8 * 68 + 4]);
            const float* av = wvA + (mtg * 32 + mi * 16 + gid) * 68 + kt * 8 + tig;
            Av[mi][0] = __float_as_uint(av[0]);
            Av[mi][1] = __float_as_uint(av[8 * 68]);
            Av[mi][2] = __float_as_uint(av[4]);
            Av[mi][3] = __float_as_uint(av[8 * 68 + 4]);
        }
#pragma unroll
        for (int ni = 0; ni < 4; ni++) {
            const float* bb = xnT + (ntg * 32 + ni * 8 + gid) * 68 + kt * 8 + tig;
            Bf[ni][0] = __float_as_uint(bb[0]);
            Bf[ni][1] = __float_as_uint(bb[4]);
        }
#pragma unroll
        for (int mi = 0; mi < 2; mi++)
#pragma unroll
            for (int ni = 0; ni < 4; ni++) {
                mma_tf32(aK[mi][ni], Ak[mi], Bf[ni]);
                mma_tf32(aV[mi][ni], Av[mi], Bf[ni]);
            }
    }

    // ---- epilogues: V -> vb (over xfl), phi(K) in regs ----
    float* vb = xfl;
#pragma unroll
    for (int ni = 0; ni < 4; ni++) {
        int l0 = ntg * 32 + ni * 8 + 2 * tig;
        float mu0 = mus[l0], mu1 = mus[l0 + 1];
        float rs0 = rss[l0], rs1 = rss[l0 + 1];
#pragma unroll
        for (int mi = 0; mi < 2; mi++) {
            int elo = mtg * 32 + mi * 16 + gid, ehi = elo + 8;
            float* cv4 = aV[mi][ni];
            float dvl = dvs[elo], cvl = cvs[elo], dvh = dvs[ehi], cvh = cvs[ehi];
            *(ull*)(vb + elo * 132 + l0) =
                pk2(fmaf(rs0, cv4[0] - mu0 * dvl, cvl), fmaf(rs1, cv4[1] - mu1 * dvl, cvl));
            *(ull*)(vb + ehi * 132 + l0) =
                pk2(fmaf(rs0, cv4[2] - mu0 * dvh, cvh), fmaf(rs1, cv4[3] - mu1 * dvh, cvh));
            float* ck4 = aK[mi][ni];
            float dkl = dks[elo], ckl = cks[elo], dkh = dks[ehi], ckh = cks[ehi];
            ck4[0] = phi_fn(fmaf(rs0, ck4[0] - mu0 * dkl, ckl));
            ck4[1] = phi_fn(fmaf(rs1, ck4[1] - mu1 * dkl, ckl));
            ck4[2] = phi_fn(fmaf(rs0, ck4[2] - mu0 * dkh, ckh));
            ck4[3] = phi_fn(fmaf(rs1, ck4[3] - mu1 * dkh, ckh));
        }
    }
    __syncthreads();   // all mma reads of xnT done
    float* kb = xnT;   // reuse as [e][l] s132
#pragma unroll
    for (int ni = 0; ni < 4; ni++) {
        int l0 = ntg * 32 + ni * 8 + 2 * tig;
#pragma unroll
        for (int mi = 0; mi < 2; mi++) {
            int elo = mtg * 32 + mi * 16 + gid, ehi = elo + 8;
            float* ck4 = aK[mi][ni];
            *(ull*)(kb + elo * 132 + l0) = pk2(ck4[0], ck4[1]);
            *(ull*)(kb + ehi * 132 + l0) = pk2(ck4[2], ck4[3]);
        }
    }
    __syncthreads();

    // ---- KV accumulation: two (hh,d,e) entries per thread ----
    {
        int hh = tid >> 5;
        int rem = tid & 31;
        int d  = rem >> 2;
        int e2 = (rem & 3) * 2;
        const float* kr  = kb + (hh * 8 + d) * 132;
        const float* vr0 = vb + (hh * 8 + e2) * 132;
        const float* vr1 = vr0 + 132;
        ull a0 = 0ULL, a1 = 0ULL;
#pragma unroll 8
        for (int j = 0; j < 128; j += 4) {
            ulonglong2 kk = *(const ulonglong2*)(kr + j);
            ulonglong2 v0 = *(const ulonglong2*)(vr0 + j);
            ulonglong2 v1 = *(const ulonglong2*)(vr1 + j);
            fma2(a0, kk.x, v0.x); fma2(a0, kk.y, v0.y);
            fma2(a1, kk.x, v1.x); fma2(a1, kk.y, v1.y);
        }
        float2 t0 = upk(a0), t1 = upk(a1);
        atomicAdd(&g_KV[(b * 8 + hh) * 64 + d * 8 + e2],     t0.x + t0.y);
        atomicAdd(&g_KV[(b * 8 + hh) * 64 + d * 8 + e2 + 1], t1.x + t1.y);
    }
    if (tid < 64) {
        const float* kr = kb + tid * 132;
        float s = 0.f;
#pragma unroll
        for (int j = 0; j < 128; j += 4) {
            float4 v = *(const float4*)(kr + j);
            s += (v.x + v.y) + (v.z + v.w);
        }
        atomicAdd(&g_Z[b * 64 + tid], s);
    }
}

// ---------------- kernel 3: Q, attention, Wo+residual, tf32-mma temporal (256 threads) ----------------
__global__ void __launch_bounds__(256, 2) k_qo(
    const float* __restrict__ x, const float* __restrict__ gamma, const float* __restrict__ beta,
    const float* __restrict__ bo, const float* __restrict__ Wlin)
{
    extern __shared__ float sm[];
    float* wq  = sm;                    // 4096 floats (Wq, then WoT)
    float* xns = sm + 4224;             // 64*SR (8448)
    float* qb  = sm + 12672;            // 64*SR; later y tile (tf32, stride 132)
    float* wls = sm;                    // Wlin slab (tf32): 96 x 132 = 12672 over wq+gap+xns
    __shared__ float mus[128], rss[128], As[64], Cs[64], dqs[64], cqs[64], bos[64];
    __shared__ __align__(16) float KVs[512];
    __shared__ float Zs[64];

    int b = blockIdx.y, tid = threadIdx.x;
    int l0b = blockIdx.x * 128;

    if (tid < 64) {
        float a = gamma[tid] * g_istd[b * 64 + tid];
        As[tid] = a;
        Cs[tid] = beta[tid] - g_mean[b * 64 + tid] * a;
        dqs[tid] = g_dq[tid]; cqs[tid] = g_cq[tid];
        bos[tid] = bo[tid];
        Zs[tid] = g_Z[b * 64 + tid];
    }
    KVs[tid] = g_KV[b * 512 + tid];
    KVs[tid + 256] = g_KV[b * 512 + 256 + tid];
#pragma unroll
    for (int i = 0; i < 4; i++)
        ((float4*)wq)[tid + i * 256] = ((const float4*)g_Wqf)[tid + i * 256];
    __syncthreads();
#pragma unroll
    for (int i = 0; i < 8; i++) {
        int idx = tid + i * 256;
        int f = idx >> 5, c = idx & 31;
        float4 v = *(const float4*)(x + ((size_t)(b * 64 + f)) * Ln + l0b + c * 4);
        float a = As[f], c0 = Cs[f];
        v.x = fmaf(v.x, a, c0); v.y = fmaf(v.y, a, c0);
        v.z = fmaf(v.z, a, c0); v.w = fmaf(v.w, a, c0);
        *(float4*)(xns + f * SR + c * 4) = v;
    }
    __syncthreads();
    if (tid < 128) {
        float s1 = 0.f, s2 = 0.f;
#pragma unroll
        for (int f = 0; f < 64; f++) { float t = xns[f * SR + tid]; s1 += t; s2 = fmaf(t, t, s2); }
        float mu = s1 * (1.f / 64.f);
        mus[tid] = mu;
        rss[tid] = rsqrtf(fmaf(-mu, mu, s2 * (1.f / 64.f)) + 1e-5f);
    }
    __syncthreads();

    int lg = tid & 15, eg = tid >> 4;
    int e0 = eg * 4;
    const float* wqp = wq + e0;

    float2 muv[4], rsv[4];
#pragma unroll
    for (int p = 0; p < 4; p++) {
        muv[p] = upk(*(const ull*)(mus + 2 * lg + 32 * p));
        rsv[p] = upk(*(const ull*)(rss + 2 * lg + 32 * p));
    }

    // ---- Q GEMM (4e x 8l) -> phi -> qb ----
    {
        const float* hb = xns + 2 * lg;
        ull a[4][4];
#pragma unroll
        for (int i = 0; i < 4; i++)
#pragma unroll
            for (int p = 0; p < 4; p++) a[i][p] = 0ULL;
#pragma unroll 4
        for (int k = 0; k < 64; k++) {
            ull h[4];
            h[0] = *(const ull*)(hb + k * SR);
            h[1] = *(const ull*)(hb + k * SR + 32);
            h[2] = *(const ull*)(hb + k * SR + 64);
            h[3] = *(const ull*)(hb + k * SR + 96);
            float4 w4 = *(const float4*)(wqp + k * 64);
            ull wd[4] = {dup(w4.x), dup(w4.y), dup(w4.z), dup(w4.w)};
#pragma unroll
            for (int i = 0; i < 4; i++)
#pragma unroll
                for (int p = 0; p < 4; p++) fma2(a[i][p], wd[i], h[p]);
        }
#pragma unroll
        for (int i = 0; i < 4; i++) {
            int e = e0 + i; float dq = dqs[e], cq = cqs[e];
#pragma unroll
            for (int p = 0; p < 4; p++) {
                float2 s = upk(a[i][p]);
                *(ull*)(qb + e * SR + 2 * lg + 32 * p) =
                    pk2(phi_fn(fmaf(rsv[p].x, s.x - muv[p].x * dq, cq)),
                        phi_fn(fmaf(rsv[p].y, s.y - muv[p].y * dq, cq)));
            }
        }
    }
    __syncthreads();   // q complete; Wq reads done

    // ---- reload w <- WoT; attention (4 heads per thread, vectorized KV) ----
#pragma unroll
    for (int i = 0; i < 4; i++)
        ((float4*)wq)[tid + i * 256] = ((const float4*)g_Wof)[tid + i * 256];
    {
        int la = tid & 127;
        int hgrp = tid >> 7;   // 0..1
#pragma unroll
        for (int t = 0; t < 4; t++) {
            int hh = hgrp * 4 + t;
            float q[8];
#pragma unroll
            for (int d = 0; d < 8; d++) q[d] = qb[(hh * 8 + d) * SR + la];
            float nrm = 1e-6f;
#pragma unroll
            for (int d = 0; d < 8; d++) nrm = fmaf(q[d], Zs[hh * 8 + d], nrm);
            float inv = 1.f / nrm;
            float s[8] = {0.f, 0.f, 0.f, 0.f, 0.f, 0.f, 0.f, 0.f};
#pragma unroll
            for (int d = 0; d < 8; d++) {
                float4 kv0 = *(const float4*)(KVs + hh * 64 + d * 8);
                float4 kv1 = *(const float4*)(KVs + hh * 64 + d * 8 + 4);
                float qd = q[d];
                s[0] = fmaf(qd, kv0.x, s[0]); s[1] = fmaf(qd, kv0.y, s[1]);
                s[2] = fmaf(qd, kv0.z, s[2]); s[3] = fmaf(qd, kv0.w, s[3]);
                s[4] = fmaf(qd, kv1.x, s[4]); s[5] = fmaf(qd, kv1.y, s[5]);
                s[6] = fmaf(qd, kv1.z, s[6]); s[7] = fmaf(qd, kv1.w, s[7]);
            }
#pragma unroll
            for (int j = 0; j < 8; j++)
                qb[(hh * 8 + j) * SR + la] = s[j] * inv;
        }
    }
    __syncthreads();

    // ---- Wo GEMM + bias + residual -> y (tf32, stride 132, same qb region) ----
    {
        const float* hb = qb + 2 * lg;
        ull a[4][4];
#pragma unroll
        for (int i = 0; i < 4; i++)
#pragma unroll
            for (int p = 0; p < 4; p++) a[i][p] = 0ULL;
#pragma unroll 4
        for (int k = 0; k < 64; k++) {
            ull h[4];
            h[0] = *(const ull*)(hb + k * SR);
            h[1] = *(const ull*)(hb + k * SR + 32);
            h[2] = *(const ull*)(hb + k * SR + 64);
            h[3] = *(const ull*)(hb + k * SR + 96);
            float4 w4 = *(const float4*)(wqp + k * 64);
            ull wd[4] = {dup(w4.x), dup(w4.y), dup(w4.z), dup(w4.w)};
#pragma unroll
            for (int i = 0; i < 4; i++)
#pragma unroll
                for (int p = 0; p < 4; p++) fma2(a[i][p], wd[i], h[p]);
        }
        ull yo[4][4];
#pragma unroll
        for (int i = 0; i < 4; i++) {
            int fo = e0 + i;
            float bb = bos[fo];
#pragma unroll
            for (int p = 0; p < 4; p++) {
                float2 r = upk(*(const ull*)(xns + fo * SR + 2 * lg + 32 * p));
                float2 s = upk(a[i][p]);
                unsigned u0 = tf32r(s.x + bb + r.x);
                unsigned u1 = tf32r(s.y + bb + r.y);
                yo[i][p] = pk2(__uint_as_float(u0), __uint_as_float(u1));
            }
        }
        __syncthreads();   // Wo GEMM qb-reads + residual xns-reads done
#pragma unroll
        for (int i = 0; i < 4; i++)
#pragma unroll
            for (int p = 0; p < 4; p++)
                *(ull*)(qb + (e0 + i) * SR + 2 * lg + 32 * p) = yo[i][p];
    }
    // ---- Wlin slab (tf32, 96 x 132-stride) into wq+xns region ----
#pragma unroll
    for (int i = 0; i < 12; i++) {
        int idx = tid + i * 256;               // 3072 float4 = 96 rows x 32
        int p = idx >> 5, c4 = idx & 31;
        float4 v = *(const float4*)(Wlin + (size_t)p * Ln + l0b + c4 * 4);
        v.x = __uint_as_float(tf32r(v.x));
        v.y = __uint_as_float(tf32r(v.y));
        v.z = __uint_as_float(tf32r(v.z));
        v.w = __uint_as_float(tf32r(v.w));
        *(float4*)(wls + p * 132 + c4 * 4) = v;
    }
    __syncthreads();

    // ---- temporal GEMM via mma.sync m16n8k8 tf32 ----
    {
        int lane = tid & 31, w = tid >> 5;
        int gid = lane >> 2, tig = lane & 3;
        int mtg = w & 1, ntg = w >> 1;          // warp: 3 m-tiles x 2 n-tiles
        float c[3][2][4];
#pragma unroll
        for (int mi = 0; mi < 3; mi++)
#pragma unroll
            for (int ni = 0; ni < 2; ni++)
#pragma unroll
                for (int q = 0; q < 4; q++) c[mi][ni][q] = 0.f;

#pragma unroll
        for (int kt = 0; kt < 16; kt++) {
            int lcol = kt * 8 + tig;
            unsigned a[3][4], bf[2][2];
#pragma unroll
            for (int mi = 0; mi < 3; mi++) {
                const float* ab = wls + (mtg * 48 + mi * 16 + gid) * 132 + lcol;
                a[mi][0] = __float_as_uint(ab[0]);
                a[mi][1] = __float_as_uint(ab[8 * 132]);
                a[mi][2] = __float_as_uint(ab[4]);
                a[mi][3] = __float_as_uint(ab[8 * 132 + 4]);
            }
#pragma unroll
            for (int ni = 0; ni < 2; ni++) {
                const float* bb = qb + (ntg * 16 + ni * 8 + gid) * 132 + lcol;
                bf[ni][0] = __float_as_uint(bb[0]);
                bf[ni][1] = __float_as_uint(bb[4]);
            }
#pragma unroll
            for (int mi = 0; mi < 3; mi++)
#pragma unroll
                for (int ni = 0; ni < 2; ni++)
                    mma_tf32(c[mi][ni], a[mi], bf[ni]);
        }
#pragma unroll
        for (int mi = 0; mi < 3; mi++) {
            int p0 = mtg * 48 + mi * 16 + gid;
#pragma unroll
            for (int ni = 0; ni < 2; ni++) {
                int f0 = ntg * 16 + ni * 8 + 2 * tig;
                float* mb = &g_M[(b * 96 + p0) * 64 + f0];
                atomicAdd(mb,              c[mi][ni][0]);
                atomicAdd(mb + 1,          c[mi][ni][1]);
                atomicAdd(mb + 8 * 64,     c[mi][ni][2]);
                atomicAdd(mb + 8 * 64 + 1, c[mi][ni][3]);
            }
        }
    }
}

// ---------------- kernel 5: denorm + projector ----------------
__global__ void k_epi(const float* __restrict__ gamma, const float* __restrict__ beta,
                      const float* __restrict__ blin, const float* __restrict__ Wp,
                      const float* __restrict__ bp, float* __restrict__ out) {
    int b = blockIdx.x, p = threadIdx.x;
    float bl = blin[p];
    float s = bp[0];
#pragma unroll
    for (int f = 0; f < 64; f++) {
        float y = g_M[(b * 96 + p) * 64 + f] + bl;
        y = (y - beta[f]) / gamma[f];
        y = fmaf(y, g_stdp[b * 64 + f], g_mean[b * 64 + f]);
        s = fmaf(y, Wp[f], s);
    }
    out[b * 96 + p] = s;
}

// ---------------- launch ----------------
extern "C" void kernel_launch(void* const* d_in, const int* in_sizes, int n_in,
                              void* d_out, int out_size) {
    (void)in_sizes; (void)n_in; (void)out_size;
    const float* x     = (const float*)d_in[0];
    const float* gamma = (const float*)d_in[1];
    const float* beta  = (const float*)d_in[2];
    const float* lnw   = (const float*)d_in[3];
    const float* lnb   = (const float*)d_in[4];
    const float* Wq    = (const float*)d_in[5];
    const float* bq    = (const float*)d_in[6];
    const float* Wk    = (const float*)d_in[7];
    const float* bk    = (const float*)d_in[8];
    const float* Wv    = (const float*)d_in[9];
    const float* bv    = (const float*)d_in[10];
    const float* Wo    = (const float*)d_in[11];
    const float* bo    = (const float*)d_in[12];
    const float* Wlin  = (const float*)d_in[13];
    const float* blin  = (const float*)d_in[14];
    const float* Wp    = (const float*)d_in[15];
    const float* bp    = (const float*)d_in[16];
    float* out = (float*)d_out;

    const int SMB_KV = (8448 + 8704 + 2 * 4352) * 4;   // 103424 B
    const int SMB_QO = (12672 + 64 * SR) * 4;          // 84480 B
    cudaFuncSetAttribute(k_kv, cudaFuncAttributeMaxDynamicSharedMemorySize, SMB_KV);
    cudaFuncSetAttribute(k_qo, cudaFuncAttributeMaxDynamicSharedMemorySize, SMB_QO);

    k_prep<<<33, 256>>>(lnw, lnb, Wq, bq, Wk, bk, Wv, bv, Wo);
    k_stats<<<Bn * Fn, 256>>>(x);
    k_kv<<<dim3(Ln / 128, Bn), 256, SMB_KV>>>(x, gamma, beta);
    k_qo<<<dim3(Ln / 128, Bn), 256, SMB_QO>>>(x, gamma, beta, bo, Wlin);
    k_epi<<<Bn, Pn>>>(gamma, beta, blin, Wp, bp, out);
}

// round 16
// speedup vs baseline: 2.0974x; 1.2194x over previous
#include <cuda_runtime.h>
#include <cstdint>

#define Bn 32
#define Fn 64
#define Ln 8192
#define Pn 96
#define SR 132    // fp32 data tile row stride (floats)

typedef unsigned long long ull;

// ---------------- scratch (device globals) ----------------
__device__ float g_mean[Bn * Fn];
__device__ float g_istd[Bn * Fn];
__device__ float g_stdp[Bn * Fn];
__device__ float g_KV[Bn * 512];
__device__ float g_Z[Bn * 64];
__device__ float g_M[Bn * Pn * Fn];
// mma A-operand weights, tf32-rounded: [out][in] row-major
__device__ float g_WqA[4096], g_WkA[4096], g_WvA[4096], g_WoA[4096];
__device__ float g_dq[64], g_cq[64], g_dk[64], g_ck[64], g_dv[64], g_cv[64];

// ---------------- helpers ----------------
__device__ __forceinline__ void fma2(ull& d, ull a, ull b) {
    asm("fma.rn.f32x2 %0, %1, %2, %0;" : "+l"(d) : "l"(a), "l"(b));
}
__device__ __forceinline__ float2 upk(ull v) {
    float2 r;
    asm("mov.b64 {%0, %1}, %2;" : "=f"(r.x), "=f"(r.y) : "l"(v));
    return r;
}
__device__ __forceinline__ ull pk2(float a, float b) {
    ull r;
    asm("mov.b64 %0, {%1, %2};" : "=l"(r) : "f"(a), "f"(b));
    return r;
}
__device__ __forceinline__ float phi_fn(float v) {
    return v > 0.f ? v + 1.f : __expf(v);   // elu(x)+1
}
__device__ __forceinline__ unsigned tf32r(float x) {
    unsigned u;
    asm("cvt.rna.tf32.f32 %0, %1;" : "=r"(u) : "f"(x));
    return u;
}
__device__ __forceinline__ float tf32f(float x) { return __uint_as_float(tf32r(x)); }
__device__ __forceinline__ void mma_tf32(float c[4], const unsigned a[4], const unsigned b[2]) {
    asm volatile(
        "mma.sync.aligned.m16n8k8.row.col.f32.tf32.tf32.f32 "
        "{%0,%1,%2,%3}, {%4,%5,%6,%7}, {%8,%9}, {%0,%1,%2,%3};"
        : "+f"(c[0]), "+f"(c[1]), "+f"(c[2]), "+f"(c[3])
        : "r"(a[0]), "r"(a[1]), "r"(a[2]), "r"(a[3]), "r"(b[0]), "r"(b[1]));
}

// ---------------- prep (block 0) + zero accumulators (blocks 1..32) ----------------
__global__ void __launch_bounds__(256) k_prep(
    const float* __restrict__ lnw, const float* __restrict__ lnb,
    const float* __restrict__ Wq, const float* __restrict__ bq,
    const float* __restrict__ Wk, const float* __restrict__ bk,
    const float* __restrict__ Wv, const float* __restrict__ bv,
    const float* __restrict__ Wo)
{
    if (blockIdx.x > 0) {
        int zb = blockIdx.x - 1;
        int base = zb * 6144;
        for (int i = threadIdx.x; i < 6144; i += 256) g_M[base + i] = 0.f;
        if (zb < 16) {
            for (int i = threadIdx.x; i < 1024; i += 256) g_KV[zb * 1024 + i] = 0.f;
        } else {
            int zz = zb - 16;
            for (int i = threadIdx.x; i < 128; i += 256) g_Z[zz * 128 + i] = 0.f;
        }
        return;
    }
    int tid = threadIdx.x;
#pragma unroll
    for (int i = 0; i < 16; i++) {
        int idx = tid + i * 256;          // idx = out*64 + in
        int f = idx & 63;
        g_WqA[idx] = tf32f(Wq[idx] * lnw[f]);
        g_WkA[idx] = tf32f(Wk[idx] * lnw[f]);
        g_WvA[idx] = tf32f(Wv[idx] * lnw[f]);
        g_WoA[idx] = tf32f(Wo[idx]);      // [fo][e] direct
    }
    if (tid < 64) {
        int e = tid;
        float dq = 0.f, cq = 0.f, dk = 0.f, ck = 0.f, dv = 0.f, cv = 0.f;
        for (int f = 0; f < 64; f++) {
            float lw = lnw[f], lb2 = lnb[f];
            float wq = Wq[e * 64 + f], wk = Wk[e * 64 + f], wv = Wv[e * 64 + f];
            dq += wq * lw;  cq = fmaf(lb2, wq, cq);
            dk += wk * lw;  ck = fmaf(lb2, wk, ck);
            dv += wv * lw;  cv = fmaf(lb2, wv, cv);
        }
        g_dq[e] = dq; g_cq[e] = cq + bq[e];
        g_dk[e] = dk; g_ck[e] = ck + bk[e];
        g_dv[e] = dv; g_cv[e] = cv + bv[e];
    }
}

// ---------------- RevIN stats per (b,f) ----------------
__global__ void __launch_bounds__(256) k_stats(const float* __restrict__ x) {
    int bf = blockIdx.x;
    const float4* p = (const float4*)(x + (size_t)bf * Ln);
    float s1 = 0.f, s2 = 0.f;
    for (int i = threadIdx.x; i < Ln / 4; i += 256) {
        float4 v = p[i];
        s1 += (v.x + v.y) + (v.z + v.w);
        s2 = fmaf(v.x, v.x, s2); s2 = fmaf(v.y, v.y, s2);
        s2 = fmaf(v.z, v.z, s2); s2 = fmaf(v.w, v.w, s2);
    }
    __shared__ float r1[256], r2[256];
    r1[threadIdx.x] = s1; r2[threadIdx.x] = s2;
    __syncthreads();
    for (int s = 128; s > 0; s >>= 1) {
        if (threadIdx.x < s) {
            r1[threadIdx.x] += r1[threadIdx.x + s];
            r2[threadIdx.x] += r2[threadIdx.x + s];
        }
        __syncthreads();
    }
    if (threadIdx.x == 0) {
        float S1 = r1[0], S2 = r2[0];
        float mean = S1 / (float)Ln;
        float var = (S2 - S1 * mean) / (float)(Ln - 1);
        var = fmaxf(var, 0.f);
        float stdp = sqrtf(var) + 1e-5f;
        g_mean[bf] = mean; g_stdp[bf] = stdp; g_istd[bf] = 1.f / stdp;
    }
}

// ---------------- kernel 2: K/V via tf32 mma + KV,Z (256 threads) — R15 verbatim ----------------
__global__ void __launch_bounds__(256, 2) k_kv(
    const float* __restrict__ x, const float* __restrict__ gamma, const float* __restrict__ beta)
{
    extern __shared__ float sm[];
    float* xfl = sm;                 // [f][l] s132 (8448); later vb [e][l] s132
    float* xnT = sm + 8448;          // [l][f] s68  (8704); later kb [e][l] s132 (8448)
    float* wkA = sm + 8448 + 8704;   // [e][f] s68 (4352)
    float* wvA = wkA + 4352;         // 4352
    __shared__ float mus[128], rss[128], As[64], Cs[64];
    __shared__ float dks[64], cks[64], dvs[64], cvs[64];

    int b = blockIdx.y, tid = threadIdx.x;
    int l0b = blockIdx.x * 128;

    if (tid < 64) {
        float a = gamma[tid] * g_istd[b * 64 + tid];
        As[tid] = a;
        Cs[tid] = beta[tid] - g_mean[b * 64 + tid] * a;
        dks[tid] = g_dk[tid]; cks[tid] = g_ck[tid];
        dvs[tid] = g_dv[tid]; cvs[tid] = g_cv[tid];
    }
#pragma unroll
    for (int i = 0; i < 4; i++) {
        int idx = tid + i * 256;
        int e = idx >> 4, c = (idx & 15) * 4;
        *(float4*)(wkA + e * 68 + c) = ((const float4*)g_WkA)[idx];
        *(float4*)(wvA + e * 68 + c) = ((const float4*)g_WvA)[idx];
    }
    __syncthreads();   // As/Cs visible to ALL threads before xn staging
#pragma unroll
    for (int i = 0; i < 8; i++) {
        int idx = tid + i * 256;
        int f = idx >> 5, c = idx & 31;
        float4 v = *(const float4*)(x + ((size_t)(b * 64 + f)) * Ln + l0b + c * 4);
        float a = As[f], c0 = Cs[f];
        v.x = fmaf(v.x, a, c0); v.y = fmaf(v.y, a, c0);
        v.z = fmaf(v.z, a, c0); v.w = fmaf(v.w, a, c0);
        *(float4*)(xfl + f * SR + c * 4) = v;
    }
    __syncthreads();
    if (tid < 128) {
        float s1 = 0.f, s2 = 0.f;
#pragma unroll
        for (int f = 0; f < 64; f++) { float t = xfl[f * SR + tid]; s1 += t; s2 = fmaf(t, t, s2); }
        float mu = s1 * (1.f / 64.f);
        mus[tid] = mu;
        rss[tid] = rsqrtf(fmaf(-mu, mu, s2 * (1.f / 64.f)) + 1e-5f);
    }
    {
        int l = tid & 127, fgrp = tid >> 7;
        float tv[32];
#pragma unroll
        for (int i = 0; i < 32; i++)
            tv[i] = tf32f(xfl[(fgrp * 32 + i) * SR + l]);
#pragma unroll
        for (int j = 0; j < 8; j++)
            *(float4*)(xnT + l * 68 + fgrp * 32 + j * 4) =
                make_float4(tv[4 * j], tv[4 * j + 1], tv[4 * j + 2], tv[4 * j + 3]);
    }
    __syncthreads();

    int lane = tid & 31, w = tid >> 5;
    int gid = lane >> 2, tig = lane & 3;
    int mtg = w & 1, ntg = w >> 1;
    float aK[2][4][4], aV[2][4][4];
#pragma unroll
    for (int mi = 0; mi < 2; mi++)
#pragma unroll
        for (int ni = 0; ni < 4; ni++)
#pragma unroll
            for (int q = 0; q < 4; q++) { aK[mi][ni][q] = 0.f; aV[mi][ni][q] = 0.f; }

#pragma unroll
    for (int kt = 0; kt < 8; kt++) {
        unsigned Ak[2][4], Av[2][4], Bf[4][2];
#pragma unroll
        for (int mi = 0; mi < 2; mi++) {
            const float* ak = wkA + (mtg * 32 + mi * 16 + gid) * 68 + kt * 8 + tig;
            Ak[mi][0] = __float_as_uint(ak[0]);
            Ak[mi][1] = __float_as_uint(ak[8 * 68]);
            Ak[mi][2] = __float_as_uint(ak[4]);
            Ak[mi][3] = __float_as_uint(ak[8 * 68 + 4]);
            const float* av = wvA + (mtg * 32 + mi * 16 + gid) * 68 + kt * 8 + tig;
            Av[mi][0] = __float_as_uint(av[0]);
            Av[mi][1] = __float_as_uint(av[8 * 68]);
            Av[mi][2] = __float_as_uint(av[4]);
            Av[mi][3] = __float_as_uint(av[8 * 68 + 4]);
        }
#pragma unroll
        for (int ni = 0; ni < 4; ni++) {
            const float* bb = xnT + (ntg * 32 + ni * 8 + gid) * 68 + kt * 8 + tig;
            Bf[ni][0] = __float_as_uint(bb[0]);
            Bf[ni][1] = __float_as_uint(bb[4]);
        }
#pragma unroll
        for (int mi = 0; mi < 2; mi++)
#pragma unroll
            for (int ni = 0; ni < 4; ni++) {
                mma_tf32(aK[mi][ni], Ak[mi], Bf[ni]);
                mma_tf32(aV[mi][ni], Av[mi], Bf[ni]);
            }
    }

    float* vb = xfl;
#pragma unroll
    for (int ni = 0; ni < 4; ni++) {
        int l0 = ntg * 32 + ni * 8 + 2 * tig;
        float mu0 = mus[l0], mu1 = mus[l0 + 1];
        float rs0 = rss[l0], rs1 = rss[l0 + 1];
#pragma unroll
        for (int mi = 0; mi < 2; mi++) {
            int elo = mtg * 32 + mi * 16 + gid, ehi = elo + 8;
            float* cv4 = aV[mi][ni];
            float dvl = dvs[elo], cvl = cvs[elo], dvh = dvs[ehi], cvh = cvs[ehi];
            *(ull*)(vb + elo * 132 + l0) =
                pk2(fmaf(rs0, cv4[0] - mu0 * dvl, cvl), fmaf(rs1, cv4[1] - mu1 * dvl, cvl));
            *(ull*)(vb + ehi * 132 + l0) =
                pk2(fmaf(rs0, cv4[2] - mu0 * dvh, cvh), fmaf(rs1, cv4[3] - mu1 * dvh, cvh));
            float* ck4 = aK[mi][ni];
            float dkl = dks[elo], ckl = cks[elo], dkh = dks[ehi], ckh = cks[ehi];
            ck4[0] = phi_fn(fmaf(rs0, ck4[0] - mu0 * dkl, ckl));
            ck4[1] = phi_fn(fmaf(rs1, ck4[1] - mu1 * dkl, ckl));
            ck4[2] = phi_fn(fmaf(rs0, ck4[2] - mu0 * dkh, ckh));
            ck4[3] = phi_fn(fmaf(rs1, ck4[3] - mu1 * dkh, ckh));
        }
    }
    __syncthreads();   // all mma reads of xnT done
    float* kb = xnT;
#pragma unroll
    for (int ni = 0; ni < 4; ni++) {
        int l0 = ntg * 32 + ni * 8 + 2 * tig;
#pragma unroll
        for (int mi = 0; mi < 2; mi++) {
            int elo = mtg * 32 + mi * 16 + gid, ehi = elo + 8;
            float* ck4 = aK[mi][ni];
            *(ull*)(kb + elo * 132 + l0) = pk2(ck4[0], ck4[1]);
            *(ull*)(kb + ehi * 132 + l0) = pk2(ck4[2], ck4[3]);
        }
    }
    __syncthreads();

    {
        int hh = tid >> 5;
        int rem = tid & 31;
        int d  = rem >> 2;
        int e2 = (rem & 3) * 2;
        const float* kr  = kb + (hh * 8 + d) * 132;
        const float* vr0 = vb + (hh * 8 + e2) * 132;
        const float* vr1 = vr0 + 132;
        ull a0 = 0ULL, a1 = 0ULL;
#pragma unroll 8
        for (int j = 0; j < 128; j += 4) {
            ulonglong2 kk = *(const ulonglong2*)(kr + j);
            ulonglong2 v0 = *(const ulonglong2*)(vr0 + j);
            ulonglong2 v1 = *(const ulonglong2*)(vr1 + j);
            fma2(a0, kk.x, v0.x); fma2(a0, kk.y, v0.y);
            fma2(a1, kk.x, v1.x); fma2(a1, kk.y, v1.y);
        }
        float2 t0 = upk(a0), t1 = upk(a1);
        atomicAdd(&g_KV[(b * 8 + hh) * 64 + d * 8 + e2],     t0.x + t0.y);
        atomicAdd(&g_KV[(b * 8 + hh) * 64 + d * 8 + e2 + 1], t1.x + t1.y);
    }
    if (tid < 64) {
        const float* kr = kb + tid * 132;
        float s = 0.f;
#pragma unroll
        for (int j = 0; j < 128; j += 4) {
            float4 v = *(const float4*)(kr + j);
            s += (v.x + v.y) + (v.z + v.w);
        }
        atomicAdd(&g_Z[b * 64 + tid], s);
    }
}

// ---------------- kernel 3: all-mma Q/attention/Wo/temporal (256 threads) ----------------
__global__ void __launch_bounds__(256, 2) k_qo(
    const float* __restrict__ x, const float* __restrict__ gamma, const float* __restrict__ beta,
    const float* __restrict__ bo, const float* __restrict__ Wlin)
{
    extern __shared__ float sm[];
    float* xfl = sm;                 // [f][l] s132 (8448); later y [fo][l] s132 (tf32)
    float* xnT = sm + 8448;          // [l][f] s68 (8704); later qT/attT [l][e] s68
    float* wA  = sm + 8448 + 8704;   // A weights s68 (4352): Wq then Wo
    float* wls = sm + 8448;          // Wlin slab (tf32) 96 x 132 = 12672 over xnT+wA
    __shared__ float mus[128], rss[128], As[64], Cs[64], dqs[64], cqs[64], bos[64];
    __shared__ __align__(16) float KVs[512];
    __shared__ float Zs[64];

    int b = blockIdx.y, tid = threadIdx.x;
    int l0b = blockIdx.x * 128;

    if (tid < 64) {
        float a = gamma[tid] * g_istd[b * 64 + tid];
        As[tid] = a;
        Cs[tid] = beta[tid] - g_mean[b * 64 + tid] * a;
        dqs[tid] = g_dq[tid]; cqs[tid] = g_cq[tid];
        bos[tid] = bo[tid];
        Zs[tid] = g_Z[b * 64 + tid];
    }
    KVs[tid] = g_KV[b * 512 + tid];
    KVs[tid + 256] = g_KV[b * 512 + 256 + tid];
#pragma unroll
    for (int i = 0; i < 4; i++) {
        int idx = tid + i * 256;
        int e = idx >> 4, c = (idx & 15) * 4;
        *(float4*)(wA + e * 68 + c) = ((const float4*)g_WqA)[idx];
    }
    __syncthreads();
#pragma unroll
    for (int i = 0; i < 8; i++) {
        int idx = tid + i * 256;
        int f = idx >> 5, c = idx & 31;
        float4 v = *(const float4*)(x + ((size_t)(b * 64 + f)) * Ln + l0b + c * 4);
        float a = As[f], c0 = Cs[f];
        v.x = fmaf(v.x, a, c0); v.y = fmaf(v.y, a, c0);
        v.z = fmaf(v.z, a, c0); v.w = fmaf(v.w, a, c0);
        *(float4*)(xfl + f * SR + c * 4) = v;
    }
    __syncthreads();
    if (tid < 128) {
        float s1 = 0.f, s2 = 0.f;
#pragma unroll
        for (int f = 0; f < 64; f++) { float t = xfl[f * SR + tid]; s1 += t; s2 = fmaf(t, t, s2); }
        float mu = s1 * (1.f / 64.f);
        mus[tid] = mu;
        rss[tid] = rsqrtf(fmaf(-mu, mu, s2 * (1.f / 64.f)) + 1e-5f);
    }
    {   // transpose xn -> xnT [l][f] s68 (tf32)
        int l = tid & 127, fgrp = tid >> 7;
        float tv[32];
#pragma unroll
        for (int i = 0; i < 32; i++)
            tv[i] = tf32f(xfl[(fgrp * 32 + i) * SR + l]);
#pragma unroll
        for (int j = 0; j < 8; j++)
            *(float4*)(xnT + l * 68 + fgrp * 32 + j * 4) =
                make_float4(tv[4 * j], tv[4 * j + 1], tv[4 * j + 2], tv[4 * j + 3]);
    }
    __syncthreads();

    int lane = tid & 31, w = tid >> 5;
    int gid = lane >> 2, tig = lane & 3;
    int mtg = w & 1, ntg = w >> 1;

    // ---- Q GEMM via mma (A=WqA, B=xnT) ----
    float aQ[2][4][4];
#pragma unroll
    for (int mi = 0; mi < 2; mi++)
#pragma unroll
        for (int ni = 0; ni < 4; ni++)
#pragma unroll
            for (int q = 0; q < 4; q++) aQ[mi][ni][q] = 0.f;
#pragma unroll
    for (int kt = 0; kt < 8; kt++) {
        unsigned Aq[2][4], Bf[4][2];
#pragma unroll
        for (int mi = 0; mi < 2; mi++) {
            const float* aq = wA + (mtg * 32 + mi * 16 + gid) * 68 + kt * 8 + tig;
            Aq[mi][0] = __float_as_uint(aq[0]);
            Aq[mi][1] = __float_as_uint(aq[8 * 68]);
            Aq[mi][2] = __float_as_uint(aq[4]);
            Aq[mi][3] = __float_as_uint(aq[8 * 68 + 4]);
        }
#pragma unroll
        for (int ni = 0; ni < 4; ni++) {
            const float* bb = xnT + (ntg * 32 + ni * 8 + gid) * 68 + kt * 8 + tig;
            Bf[ni][0] = __float_as_uint(bb[0]);
            Bf[ni][1] = __float_as_uint(bb[4]);
        }
#pragma unroll
        for (int mi = 0; mi < 2; mi++)
#pragma unroll
            for (int ni = 0; ni < 4; ni++)
                mma_tf32(aQ[mi][ni], Aq[mi], Bf[ni]);
    }
    __syncthreads();   // all xnT reads done before qT scatter overwrites buf2

    // ---- epilogue: phi, tf32, scatter TRANSPOSED into qT [l][e] s68 ----
    float* qT = xnT;
#pragma unroll
    for (int ni = 0; ni < 4; ni++) {
        int l0 = ntg * 32 + ni * 8 + 2 * tig;
        float mu0 = mus[l0], mu1 = mus[l0 + 1];
        float rs0 = rss[l0], rs1 = rss[l0 + 1];
#pragma unroll
        for (int mi = 0; mi < 2; mi++) {
            int elo = mtg * 32 + mi * 16 + gid, ehi = elo + 8;
            float* c4 = aQ[mi][ni];
            qT[l0 * 68 + elo]       = tf32f(phi_fn(fmaf(rs0, c4[0] - mu0 * dqs[elo], cqs[elo])));
            qT[(l0 + 1) * 68 + elo] = tf32f(phi_fn(fmaf(rs1, c4[1] - mu1 * dqs[elo], cqs[elo])));
            qT[l0 * 68 + ehi]       = tf32f(phi_fn(fmaf(rs0, c4[2] - mu0 * dqs[ehi], cqs[ehi])));
            qT[(l0 + 1) * 68 + ehi] = tf32f(phi_fn(fmaf(rs1, c4[3] - mu1 * dqs[ehi], cqs[ehi])));
        }
    }
    // restage wA <- WoA (Wq reads done at the pre-scatter sync)
#pragma unroll
    for (int i = 0; i < 4; i++) {
        int idx = tid + i * 256;
        int e = idx >> 4, c = (idx & 15) * 4;
        *(float4*)(wA + e * 68 + c) = ((const float4*)g_WoA)[idx];
    }
    __syncthreads();

    // ---- attention: each thread owns half a qT row (4 heads), in place ----
    {
        int la = tid & 127, hgrp = tid >> 7;
        float* row = qT + la * 68 + hgrp * 32;
#pragma unroll
        for (int t = 0; t < 4; t++) {
            int hh = hgrp * 4 + t;
            float4 q0 = *(const float4*)(row + t * 8);
            float4 q1 = *(const float4*)(row + t * 8 + 4);
            float q[8] = {q0.x, q0.y, q0.z, q0.w, q1.x, q1.y, q1.z, q1.w};
            float nrm = 1e-6f;
#pragma unroll
            for (int d = 0; d < 8; d++) nrm = fmaf(q[d], Zs[hh * 8 + d], nrm);
            float inv = 1.f / nrm;
            float s[8] = {0.f, 0.f, 0.f, 0.f, 0.f, 0.f, 0.f, 0.f};
#pragma unroll
            for (int d = 0; d < 8; d++) {
                float4 kv0 = *(const float4*)(KVs + hh * 64 + d * 8);
                float4 kv1 = *(const float4*)(KVs + hh * 64 + d * 8 + 4);
                float qd = q[d];
                s[0] = fmaf(qd, kv0.x, s[0]); s[1] = fmaf(qd, kv0.y, s[1]);
                s[2] = fmaf(qd, kv0.z, s[2]); s[3] = fmaf(qd, kv0.w, s[3]);
                s[4] = fmaf(qd, kv1.x, s[4]); s[5] = fmaf(qd, kv1.y, s[5]);
                s[6] = fmaf(qd, kv1.z, s[6]); s[7] = fmaf(qd, kv1.w, s[7]);
            }
            *(float4*)(row + t * 8) = make_float4(
                tf32f(s[0] * inv), tf32f(s[1] * inv), tf32f(s[2] * inv), tf32f(s[3] * inv));
            *(float4*)(row + t * 8 + 4) = make_float4(
                tf32f(s[4] * inv), tf32f(s[5] * inv), tf32f(s[6] * inv), tf32f(s[7] * inv));
        }
    }
    __syncthreads();

    // ---- Wo GEMM via mma (A=WoA, B=attT=qT) ----
    float aO[2][4][4];
#pragma unroll
    for (int mi = 0; mi < 2; mi++)
#pragma unroll
        for (int ni = 0; ni < 4; ni++)
#pragma unroll
            for (int q = 0; q < 4; q++) aO[mi][ni][q] = 0.f;
#pragma unroll
    for (int kt = 0; kt < 8; kt++) {
        unsigned Ao[2][4], Bf[4][2];
#pragma unroll
        for (int mi = 0; mi < 2; mi++) {
            const float* ao = wA + (mtg * 32 + mi * 16 + gid) * 68 + kt * 8 + tig;
            Ao[mi][0] = __float_as_uint(ao[0]);
            Ao[mi][1] = __float_as_uint(ao[8 * 68]);
            Ao[mi][2] = __float_as_uint(ao[4]);
            Ao[mi][3] = __float_as_uint(ao[8 * 68 + 4]);
        }
#pragma unroll
        for (int ni = 0; ni < 4; ni++) {
            const float* bb = qT + (ntg * 32 + ni * 8 + gid) * 68 + kt * 8 + tig;
            Bf[ni][0] = __float_as_uint(bb[0]);
            Bf[ni][1] = __float_as_uint(bb[4]);
        }
#pragma unroll
        for (int mi = 0; mi < 2; mi++)
#pragma unroll
            for (int ni = 0; ni < 4; ni++)
                mma_tf32(aO[mi][ni], Ao[mi], Bf[ni]);
    }
    __syncthreads();   // all attT/wA reads done before Wlin slab overwrites them

    // ---- epilogue: y = c + bo + residual(x) -> tf32 -> buf1; stage Wlin slab ----
    float* yb = xfl;
#pragma unroll
    for (int mi = 0; mi < 2; mi++) {
        int fl = mtg * 32 + mi * 16 + gid, fh = fl + 8;
        float bbl = bos[fl], bbh = bos[fh];
        float al = As[fl], cl = Cs[fl], ah = As[fh], ch = Cs[fh];
        const float* xl = x + ((size_t)(b * 64 + fl)) * Ln + l0b;
        const float* xh = x + ((size_t)(b * 64 + fh)) * Ln + l0b;
#pragma unroll
        for (int ni = 0; ni < 4; ni++) {
            int l0 = ntg * 32 + ni * 8 + 2 * tig;
            float2 rl = *(const float2*)(xl + l0);
            float2 rh = *(const float2*)(xh + l0);
            float* c4 = aO[mi][ni];
            *(ull*)(yb + fl * 132 + l0) = pk2(
                tf32f(c4[0] + bbl + fmaf(rl.x, al, cl)),
                tf32f(c4[1] + bbl + fmaf(rl.y, al, cl)));
            *(ull*)(yb + fh * 132 + l0) = pk2(
                tf32f(c4[2] + bbh + fmaf(rh.x, ah, ch)),
                tf32f(c4[3] + bbh + fmaf(rh.y, ah, ch)));
        }
    }
#pragma unroll
    for (int i = 0; i < 12; i++) {
        int idx = tid + i * 256;               // 3072 float4 = 96 rows x 32
        int p = idx >> 5, c4 = idx & 31;
        float4 v = *(const float4*)(Wlin + (size_t)p * Ln + l0b + c4 * 4);
        v.x = tf32f(v.x); v.y = tf32f(v.y); v.z = tf32f(v.z); v.w = tf32f(v.w);
        *(float4*)(wls + p * 132 + c4 * 4) = v;
    }
    __syncthreads();

    // ---- temporal GEMM via mma (A=Wlin s132, B=y s132) ----
    {
        int mtg2 = w & 1, ntg2 = w >> 1;
        float c[3][2][4];
#pragma unroll
        for (int mi = 0; mi < 3; mi++)
#pragma unroll
            for (int ni = 0; ni < 2; ni++)
#pragma unroll
                for (int q = 0; q < 4; q++) c[mi][ni][q] = 0.f;
#pragma unroll
        for (int kt = 0; kt < 16; kt++) {
            int lcol = kt * 8 + tig;
            unsigned a[3][4], bf[2][2];
#pragma unroll
            for (int mi = 0; mi < 3; mi++) {
                const float* ab = wls + (mtg2 * 48 + mi * 16 + gid) * 132 + lcol;
                a[mi][0] = __float_as_uint(ab[0]);
                a[mi][1] = __float_as_uint(ab[8 * 132]);
                a[mi][2] = __float_as_uint(ab[4]);
                a[mi][3] = __float_as_uint(ab[8 * 132 + 4]);
            }
#pragma unroll
            for (int ni = 0; ni < 2; ni++) {
                const float* bb = yb + (ntg2 * 16 + ni * 8 + gid) * 132 + lcol;
                bf[ni][0] = __float_as_uint(bb[0]);
                bf[ni][1] = __float_as_uint(bb[4]);
            }
#pragma unroll
            for (int mi = 0; mi < 3; mi++)
#pragma unroll
                for (int ni = 0; ni < 2; ni++)
                    mma_tf32(c[mi][ni], a[mi], bf[ni]);
        }
#pragma unroll
        for (int mi = 0; mi < 3; mi++) {
            int p0 = mtg2 * 48 + mi * 16 + gid;
#pragma unroll
            for (int ni = 0; ni < 2; ni++) {
                int f0 = ntg2 * 16 + ni * 8 + 2 * tig;
                float* mb = &g_M[(b * 96 + p0) * 64 + f0];
                atomicAdd(mb,              c[mi][ni][0]);
                atomicAdd(mb + 1,          c[mi][ni][1]);
                atomicAdd(mb + 8 * 64,     c[mi][ni][2]);
                atomicAdd(mb + 8 * 64 + 1, c[mi][ni][3]);
            }
        }
    }
}

// ---------------- kernel 5: denorm + projector ----------------
__global__ void k_epi(const float* __restrict__ gamma, const float* __restrict__ beta,
                      const float* __restrict__ blin, const float* __restrict__ Wp,
                      const float* __restrict__ bp, float* __restrict__ out) {
    int b = blockIdx.x, p = threadIdx.x;
    float bl = blin[p];
    float s = bp[0];
#pragma unroll
    for (int f = 0; f < 64; f++) {
        float y = g_M[(b * 96 + p) * 64 + f] + bl;
        y = (y - beta[f]) / gamma[f];
        y = fmaf(y, g_stdp[b * 64 + f], g_mean[b * 64 + f]);
        s = fmaf(y, Wp[f], s);
    }
    out[b * 96 + p] = s;
}

// ---------------- launch ----------------
extern "C" void kernel_launch(void* const* d_in, const int* in_sizes, int n_in,
                              void* d_out, int out_size) {
    (void)in_sizes; (void)n_in; (void)out_size;
    const float* x     = (const float*)d_in[0];
    const float* gamma = (const float*)d_in[1];
    const float* beta  = (const float*)d_in[2];
    const float* lnw   = (const float*)d_in[3];
    const float* lnb   = (const float*)d_in[4];
    const float* Wq    = (const float*)d_in[5];
    const float* bq    = (const float*)d_in[6];
    const float* Wk    = (const float*)d_in[7];
    const float* bk    = (const float*)d_in[8];
    const float* Wv    = (const float*)d_in[9];
    const float* bv    = (const float*)d_in[10];
    const float* Wo    = (const float*)d_in[11];
    const float* bo    = (const float*)d_in[12];
    const float* Wlin  = (const float*)d_in[13];
    const float* blin  = (const float*)d_in[14];
    const float* Wp    = (const float*)d_in[15];
    const float* bp    = (const float*)d_in[16];
    float* out = (float*)d_out;

    const int SMB_KV = (8448 + 8704 + 2 * 4352) * 4;   // 103424 B
    const int SMB_QO = (8448 + 8704 + 4352) * 4;       // 86016 B
    cudaFuncSetAttribute(k_kv, cudaFuncAttributeMaxDynamicSharedMemorySize, SMB_KV);
    cudaFuncSetAttribute(k_qo, cudaFuncAttributeMaxDynamicSharedMemorySize, SMB_QO);

    k_prep<<<33, 256>>>(lnw, lnb, Wq, bq, Wk, bk, Wv, bv, Wo);
    k_stats<<<Bn * Fn, 256>>>(x);
    k_kv<<<dim3(Ln / 128, Bn), 256, SMB_KV>>>(x, gamma, beta);
    k_qo<<<dim3(Ln / 128, Bn), 256, SMB_QO>>>(x, gamma, beta, bo, Wlin);
    k_epi<<<Bn, Pn>>>(gamma, beta, blin, Wp, bp, out);
}

// round 17
// speedup vs baseline: 2.1960x; 1.0470x over previous
#include <cuda_runtime.h>
#include <cstdint>

#define Bn 32
#define Fn 64
#define Ln 8192
#define Pn 96
#define SR 132    // fp32 data tile row stride (floats)

typedef unsigned long long ull;

// ---------------- scratch (device globals) ----------------
__device__ float g_mean[Bn * Fn];
__device__ float g_istd[Bn * Fn];
__device__ float g_stdp[Bn * Fn];
__device__ float g_KV[Bn * 512];
__device__ float g_Z[Bn * 64];
__device__ float g_M[Bn * Pn * Fn];
// mma A-operand weights, tf32-rounded: [out][in] row-major
__device__ float g_WqA[4096], g_WkA[4096], g_WvA[4096], g_WoA[4096];
__device__ float g_dq[64], g_cq[64], g_dk[64], g_ck[64], g_dv[64], g_cv[64];

// ---------------- helpers ----------------
__device__ __forceinline__ ull pk2(float a, float b) {
    ull r;
    asm("mov.b64 %0, {%1, %2};" : "=l"(r) : "f"(a), "f"(b));
    return r;
}
__device__ __forceinline__ float phi_fn(float v) {
    return v > 0.f ? v + 1.f : __expf(v);   // elu(x)+1
}
__device__ __forceinline__ unsigned tf32r(float x) {
    unsigned u;
    asm("cvt.rna.tf32.f32 %0, %1;" : "=r"(u) : "f"(x));
    return u;
}
__device__ __forceinline__ float tf32f(float x) { return __uint_as_float(tf32r(x)); }
__device__ __forceinline__ void mma_tf32(float c[4], const unsigned a[4], const unsigned b[2]) {
    asm volatile(
        "mma.sync.aligned.m16n8k8.row.col.f32.tf32.tf32.f32 "
        "{%0,%1,%2,%3}, {%4,%5,%6,%7}, {%8,%9}, {%0,%1,%2,%3};"
        : "+f"(c[0]), "+f"(c[1]), "+f"(c[2]), "+f"(c[3])
        : "r"(a[0]), "r"(a[1]), "r"(a[2]), "r"(a[3]), "r"(b[0]), "r"(b[1]));
}

// ---------------- prep (block 0) + zero accumulators (blocks 1..32) ----------------
__global__ void __launch_bounds__(256) k_prep(
    const float* __restrict__ lnw, const float* __restrict__ lnb,
    const float* __restrict__ Wq, const float* __restrict__ bq,
    const float* __restrict__ Wk, const float* __restrict__ bk,
    const float* __restrict__ Wv, const float* __restrict__ bv,
    const float* __restrict__ Wo)
{
    if (blockIdx.x > 0) {
        int zb = blockIdx.x - 1;
        int base = zb * 6144;
        for (int i = threadIdx.x; i < 6144; i += 256) g_M[base + i] = 0.f;
        if (zb < 16) {
            for (int i = threadIdx.x; i < 1024; i += 256) g_KV[zb * 1024 + i] = 0.f;
        } else {
            int zz = zb - 16;
            for (int i = threadIdx.x; i < 128; i += 256) g_Z[zz * 128 + i] = 0.f;
        }
        return;
    }
    int tid = threadIdx.x;
#pragma unroll
    for (int i = 0; i < 16; i++) {
        int idx = tid + i * 256;          // idx = out*64 + in
        int f = idx & 63;
        g_WqA[idx] = tf32f(Wq[idx] * lnw[f]);
        g_WkA[idx] = tf32f(Wk[idx] * lnw[f]);
        g_WvA[idx] = tf32f(Wv[idx] * lnw[f]);
        g_WoA[idx] = tf32f(Wo[idx]);      // [fo][e] direct
    }
    if (tid < 64) {
        int e = tid;
        float dq = 0.f, cq = 0.f, dk = 0.f, ck = 0.f, dv = 0.f, cv = 0.f;
        for (int f = 0; f < 64; f++) {
            float lw = lnw[f], lb2 = lnb[f];
            float wq = Wq[e * 64 + f], wk = Wk[e * 64 + f], wv = Wv[e * 64 + f];
            dq += wq * lw;  cq = fmaf(lb2, wq, cq);
            dk += wk * lw;  ck = fmaf(lb2, wk, ck);
            dv += wv * lw;  cv = fmaf(lb2, wv, cv);
        }
        g_dq[e] = dq; g_cq[e] = cq + bq[e];
        g_dk[e] = dk; g_ck[e] = ck + bk[e];
        g_dv[e] = dv; g_cv[e] = cv + bv[e];
    }
}

// ---------------- RevIN stats per (b,f) ----------------
__global__ void __launch_bounds__(256) k_stats(const float* __restrict__ x) {
    int bf = blockIdx.x;
    const float4* p = (const float4*)(x + (size_t)bf * Ln);
    float s1 = 0.f, s2 = 0.f;
    for (int i = threadIdx.x; i < Ln / 4; i += 256) {
        float4 v = p[i];
        s1 += (v.x + v.y) + (v.z + v.w);
        s2 = fmaf(v.x, v.x, s2); s2 = fmaf(v.y, v.y, s2);
        s2 = fmaf(v.z, v.z, s2); s2 = fmaf(v.w, v.w, s2);
    }
    __shared__ float r1[256], r2[256];
    r1[threadIdx.x] = s1; r2[threadIdx.x] = s2;
    __syncthreads();
    for (int s = 128; s > 0; s >>= 1) {
        if (threadIdx.x < s) {
            r1[threadIdx.x] += r1[threadIdx.x + s];
            r2[threadIdx.x] += r2[threadIdx.x + s];
        }
        __syncthreads();
    }
    if (threadIdx.x == 0) {
        float S1 = r1[0], S2 = r2[0];
        float mean = S1 / (float)Ln;
        float var = (S2 - S1 * mean) / (float)(Ln - 1);
        var = fmaxf(var, 0.f);
        float stdp = sqrtf(var) + 1e-5f;
        g_mean[bf] = mean; g_stdp[bf] = stdp; g_istd[bf] = 1.f / stdp;
    }
}

// ---------------- kernel 2: K/V via tf32 mma + mma KV + Z (256 threads) ----------------
__global__ void __launch_bounds__(256, 2) k_kv(
    const float* __restrict__ x, const float* __restrict__ gamma, const float* __restrict__ beta)
{
    extern __shared__ float sm[];
    float* xfl = sm;                 // [f][l] s132 (8448); later vb [e][l] s132 (tf32)
    float* xnT = sm + 8448;          // [l][f] s68  (8704); later kb [e][l] s132 (tf32)
    float* wkA = sm + 8448 + 8704;   // [e][f] s68 (4352)
    float* wvA = wkA + 4352;         // 4352
    __shared__ float mus[128], rss[128], As[64], Cs[64];
    __shared__ float dks[64], cks[64], dvs[64], cvs[64];

    int b = blockIdx.y, tid = threadIdx.x;
    int l0b = blockIdx.x * 128;

    if (tid < 64) {
        float a = gamma[tid] * g_istd[b * 64 + tid];
        As[tid] = a;
        Cs[tid] = beta[tid] - g_mean[b * 64 + tid] * a;
        dks[tid] = g_dk[tid]; cks[tid] = g_ck[tid];
        dvs[tid] = g_dv[tid]; cvs[tid] = g_cv[tid];
    }
#pragma unroll
    for (int i = 0; i < 4; i++) {
        int idx = tid + i * 256;
        int e = idx >> 4, c = (idx & 15) * 4;
        *(float4*)(wkA + e * 68 + c) = ((const float4*)g_WkA)[idx];
        *(float4*)(wvA + e * 68 + c) = ((const float4*)g_WvA)[idx];
    }
    __syncthreads();   // As/Cs visible to ALL threads before xn staging
#pragma unroll
    for (int i = 0; i < 8; i++) {
        int idx = tid + i * 256;
        int f = idx >> 5, c = idx & 31;
        float4 v = *(const float4*)(x + ((size_t)(b * 64 + f)) * Ln + l0b + c * 4);
        float a = As[f], c0 = Cs[f];
        v.x = fmaf(v.x, a, c0); v.y = fmaf(v.y, a, c0);
        v.z = fmaf(v.z, a, c0); v.w = fmaf(v.w, a, c0);
        *(float4*)(xfl + f * SR + c * 4) = v;
    }
    __syncthreads();
    if (tid < 128) {
        float s1 = 0.f, s2 = 0.f;
#pragma unroll
        for (int f = 0; f < 64; f++) { float t = xfl[f * SR + tid]; s1 += t; s2 = fmaf(t, t, s2); }
        float mu = s1 * (1.f / 64.f);
        mus[tid] = mu;
        rss[tid] = rsqrtf(fmaf(-mu, mu, s2 * (1.f / 64.f)) + 1e-5f);
    }
    {
        int l = tid & 127, fgrp = tid >> 7;
        float tv[32];
#pragma unroll
        for (int i = 0; i < 32; i++)
            tv[i] = tf32f(xfl[(fgrp * 32 + i) * SR + l]);
#pragma unroll
        for (int j = 0; j < 8; j++)
            *(float4*)(xnT + l * 68 + fgrp * 32 + j * 4) =
                make_float4(tv[4 * j], tv[4 * j + 1], tv[4 * j + 2], tv[4 * j + 3]);
    }
    __syncthreads();

    int lane = tid & 31, w = tid >> 5;
    int gid = lane >> 2, tig = lane & 3;
    int mtg = w & 1, ntg = w >> 1;
    float aK[2][4][4], aV[2][4][4];
#pragma unroll
    for (int mi = 0; mi < 2; mi++)
#pragma unroll
        for (int ni = 0; ni < 4; ni++)
#pragma unroll
            for (int q = 0; q < 4; q++) { aK[mi][ni][q] = 0.f; aV[mi][ni][q] = 0.f; }

#pragma unroll
    for (int kt = 0; kt < 8; kt++) {
        unsigned Ak[2][4], Av[2][4], Bf[4][2];
#pragma unroll
        for (int mi = 0; mi < 2; mi++) {
            const float* ak = wkA + (mtg * 32 + mi * 16 + gid) * 68 + kt * 8 + tig;
            Ak[mi][0] = __float_as_uint(ak[0]);
            Ak[mi][1] = __float_as_uint(ak[8 * 68]);
            Ak[mi][2] = __float_as_uint(ak[4]);
            Ak[mi][3] = __float_as_uint(ak[8 * 68 + 4]);
            const float* av = wvA + (mtg * 32 + mi * 16 + gid) * 68 + kt * 8 + tig;
            Av[mi][0] = __float_as_uint(av[0]);
            Av[mi][1] = __float_as_uint(av[8 * 68]);
            Av[mi][2] = __float_as_uint(av[4]);
            Av[mi][3] = __float_as_uint(av[8 * 68 + 4]);
        }
#pragma unroll
        for (int ni = 0; ni < 4; ni++) {
            const float* bb = xnT + (ntg * 32 + ni * 8 + gid) * 68 + kt * 8 + tig;
            Bf[ni][0] = __float_as_uint(bb[0]);
            Bf[ni][1] = __float_as_uint(bb[4]);
        }
#pragma unroll
        for (int mi = 0; mi < 2; mi++)
#pragma unroll
            for (int ni = 0; ni < 4; ni++) {
                mma_tf32(aK[mi][ni], Ak[mi], Bf[ni]);
                mma_tf32(aV[mi][ni], Av[mi], Bf[ni]);
            }
    }

    // ---- epilogues: V -> vb (tf32), phi(K) (tf32) in regs ----
    float* vb = xfl;
#pragma unroll
    for (int ni = 0; ni < 4; ni++) {
        int l0 = ntg * 32 + ni * 8 + 2 * tig;
        float mu0 = mus[l0], mu1 = mus[l0 + 1];
        float rs0 = rss[l0], rs1 = rss[l0 + 1];
#pragma unroll
        for (int mi = 0; mi < 2; mi++) {
            int elo = mtg * 32 + mi * 16 + gid, ehi = elo + 8;
            float* cv4 = aV[mi][ni];
            float dvl = dvs[elo], cvl = cvs[elo], dvh = dvs[ehi], cvh = cvs[ehi];
            *(ull*)(vb + elo * 132 + l0) =
                pk2(tf32f(fmaf(rs0, cv4[0] - mu0 * dvl, cvl)),
                    tf32f(fmaf(rs1, cv4[1] - mu1 * dvl, cvl)));
            *(ull*)(vb + ehi * 132 + l0) =
                pk2(tf32f(fmaf(rs0, cv4[2] - mu0 * dvh, cvh)),
                    tf32f(fmaf(rs1, cv4[3] - mu1 * dvh, cvh)));
            float* ck4 = aK[mi][ni];
            float dkl = dks[elo], ckl = cks[elo], dkh = dks[ehi], ckh = cks[ehi];
            ck4[0] = tf32f(phi_fn(fmaf(rs0, ck4[0] - mu0 * dkl, ckl)));
            ck4[1] = tf32f(phi_fn(fmaf(rs1, ck4[1] - mu1 * dkl, ckl)));
            ck4[2] = tf32f(phi_fn(fmaf(rs0, ck4[2] - mu0 * dkh, ckh)));
            ck4[3] = tf32f(phi_fn(fmaf(rs1, ck4[3] - mu1 * dkh, ckh)));
        }
    }
    __syncthreads();   // all mma reads of xnT done
    float* kb = xnT;   // reuse as [e][l] s132 (tf32)
#pragma unroll
    for (int ni = 0; ni < 4; ni++) {
        int l0 = ntg * 32 + ni * 8 + 2 * tig;
#pragma unroll
        for (int mi = 0; mi < 2; mi++) {
            int elo = mtg * 32 + mi * 16 + gid, ehi = elo + 8;
            float* ck4 = aK[mi][ni];
            *(ull*)(kb + elo * 132 + l0) = pk2(ck4[0], ck4[1]);
            *(ull*)(kb + ehi * 132 + l0) = pk2(ck4[2], ck4[3]);
        }
    }
    __syncthreads();

    // ---- KV accumulation via block-diagonal tf32 mma ----
    // warp w: m-tile mi2 = w>>1 (heads 2mi2, 2mi2+1), B head = 2mi2 + (w&1)
    {
        int mi2 = w >> 1, nin = w & 1;
        int head = 2 * mi2 + nin;
        float c[4] = {0.f, 0.f, 0.f, 0.f};
        const float* arow = kb + (mi2 * 16 + gid) * 132;
        const float* brow = vb + (head * 8 + gid) * 132;
#pragma unroll
        for (int kt = 0; kt < 16; kt++) {
            int lcol = kt * 8 + tig;
            unsigned a[4], bfr[2];
            a[0] = __float_as_uint(arow[lcol]);
            a[1] = __float_as_uint(arow[8 * 132 + lcol]);
            a[2] = __float_as_uint(arow[lcol + 4]);
            a[3] = __float_as_uint(arow[8 * 132 + lcol + 4]);
            bfr[0] = __float_as_uint(brow[lcol]);
            bfr[1] = __float_as_uint(brow[lcol + 4]);
            mma_tf32(c, a, bfr);
        }
        // valid C rows: nin==0 -> rows gid (head 2mi2, d=gid) -> c[0],c[1]
        //               nin==1 -> rows gid+8 (head 2mi2+1, d=gid) -> c[2],c[3]
        float* kvb = &g_KV[(b * 8 + head) * 64 + gid * 8 + 2 * tig];
        if (nin == 0) {
            atomicAdd(kvb,     c[0]);
            atomicAdd(kvb + 1, c[1]);
        } else {
            atomicAdd(kvb,     c[2]);
            atomicAdd(kvb + 1, c[3]);
        }
    }
    // ---- Z (first 64 threads) ----
    if (tid < 64) {
        const float* kr = kb + tid * 132;
        float s = 0.f;
#pragma unroll
        for (int j = 0; j < 128; j += 4) {
            float4 v = *(const float4*)(kr + j);
            s += (v.x + v.y) + (v.z + v.w);
        }
        atomicAdd(&g_Z[b * 64 + tid], s);
    }
}

// ---------------- kernel 3: all-mma Q/attention/Wo/temporal (256 threads) — R16 verbatim ----------------
__global__ void __launch_bounds__(256, 2) k_qo(
    const float* __restrict__ x, const float* __restrict__ gamma, const float* __restrict__ beta,
    const float* __restrict__ bo, const float* __restrict__ Wlin)
{
    extern __shared__ float sm[];
    float* xfl = sm;                 // [f][l] s132 (8448); later y [fo][l] s132 (tf32)
    float* xnT = sm + 8448;          // [l][f] s68 (8704); later qT/attT [l][e] s68
    float* wA  = sm + 8448 + 8704;   // A weights s68 (4352): Wq then Wo
    float* wls = sm + 8448;          // Wlin slab (tf32) 96 x 132 = 12672 over xnT+wA
    __shared__ float mus[128], rss[128], As[64], Cs[64], dqs[64], cqs[64], bos[64];
    __shared__ __align__(16) float KVs[512];
    __shared__ float Zs[64];

    int b = blockIdx.y, tid = threadIdx.x;
    int l0b = blockIdx.x * 128;

    if (tid < 64) {
        float a = gamma[tid] * g_istd[b * 64 + tid];
        As[tid] = a;
        Cs[tid] = beta[tid] - g_mean[b * 64 + tid] * a;
        dqs[tid] = g_dq[tid]; cqs[tid] = g_cq[tid];
        bos[tid] = bo[tid];
        Zs[tid] = g_Z[b * 64 + tid];
    }
    KVs[tid] = g_KV[b * 512 + tid];
    KVs[tid + 256] = g_KV[b * 512 + 256 + tid];
#pragma unroll
    for (int i = 0; i < 4; i++) {
        int idx = tid + i * 256;
        int e = idx >> 4, c = (idx & 15) * 4;
        *(float4*)(wA + e * 68 + c) = ((const float4*)g_WqA)[idx];
    }
    __syncthreads();
#pragma unroll
    for (int i = 0; i < 8; i++) {
        int idx = tid + i * 256;
        int f = idx >> 5, c = idx & 31;
        float4 v = *(const float4*)(x + ((size_t)(b * 64 + f)) * Ln + l0b + c * 4);
        float a = As[f], c0 = Cs[f];
        v.x = fmaf(v.x, a, c0); v.y = fmaf(v.y, a, c0);
        v.z = fmaf(v.z, a, c0); v.w = fmaf(v.w, a, c0);
        *(float4*)(xfl + f * SR + c * 4) = v;
    }
    __syncthreads();
    if (tid < 128) {
        float s1 = 0.f, s2 = 0.f;
#pragma unroll
        for (int f = 0; f < 64; f++) { float t = xfl[f * SR + tid]; s1 += t; s2 = fmaf(t, t, s2); }
        float mu = s1 * (1.f / 64.f);
        mus[tid] = mu;
        rss[tid] = rsqrtf(fmaf(-mu, mu, s2 * (1.f / 64.f)) + 1e-5f);
    }
    {   // transpose xn -> xnT [l][f] s68 (tf32)
        int l = tid & 127, fgrp = tid >> 7;
        float tv[32];
#pragma unroll
        for (int i = 0; i < 32; i++)
            tv[i] = tf32f(xfl[(fgrp * 32 + i) * SR + l]);
#pragma unroll
        for (int j = 0; j < 8; j++)
            *(float4*)(xnT + l * 68 + fgrp * 32 + j * 4) =
                make_float4(tv[4 * j], tv[4 * j + 1], tv[4 * j + 2], tv[4 * j + 3]);
    }
    __syncthreads();

    int lane = tid & 31, w = tid >> 5;
    int gid = lane >> 2, tig = lane & 3;
    int mtg = w & 1, ntg = w >> 1;

    // ---- Q GEMM via mma (A=WqA, B=xnT) ----
    float aQ[2][4][4];
#pragma unroll
    for (int mi = 0; mi < 2; mi++)
#pragma unroll
        for (int ni = 0; ni < 4; ni++)
#pragma unroll
            for (int q = 0; q < 4; q++) aQ[mi][ni][q] = 0.f;
#pragma unroll
    for (int kt = 0; kt < 8; kt++) {
        unsigned Aq[2][4], Bf[4][2];
#pragma unroll
        for (int mi = 0; mi < 2; mi++) {
            const float* aq = wA + (mtg * 32 + mi * 16 + gid) * 68 + kt * 8 + tig;
            Aq[mi][0] = __float_as_uint(aq[0]);
            Aq[mi][1] = __float_as_uint(aq[8 * 68]);
            Aq[mi][2] = __float_as_uint(aq[4]);
            Aq[mi][3] = __float_as_uint(aq[8 * 68 + 4]);
        }
#pragma unroll
        for (int ni = 0; ni < 4; ni++) {
            const float* bb = xnT + (ntg * 32 + ni * 8 + gid) * 68 + kt * 8 + tig;
            Bf[ni][0] = __float_as_uint(bb[0]);
            Bf[ni][1] = __float_as_uint(bb[4]);
        }
#pragma unroll
        for (int mi = 0; mi < 2; mi++)
#pragma unroll
            for (int ni = 0; ni < 4; ni++)
                mma_tf32(aQ[mi][ni], Aq[mi], Bf[ni]);
    }
    __syncthreads();   // all xnT reads done before qT scatter overwrites buf2

    // ---- epilogue: phi, tf32, scatter TRANSPOSED into qT [l][e] s68 ----
    float* qT = xnT;
#pragma unroll
    for (int ni = 0; ni < 4; ni++) {
        int l0 = ntg * 32 + ni * 8 + 2 * tig;
        float mu0 = mus[l0], mu1 = mus[l0 + 1];
        float rs0 = rss[l0], rs1 = rss[l0 + 1];
#pragma unroll
        for (int mi = 0; mi < 2; mi++) {
            int elo = mtg * 32 + mi * 16 + gid, ehi = elo + 8;
            float* c4 = aQ[mi][ni];
            qT[l0 * 68 + elo]       = tf32f(phi_fn(fmaf(rs0, c4[0] - mu0 * dqs[elo], cqs[elo])));
            qT[(l0 + 1) * 68 + elo] = tf32f(phi_fn(fmaf(rs1, c4[1] - mu1 * dqs[elo], cqs[elo])));
            qT[l0 * 68 + ehi]       = tf32f(phi_fn(fmaf(rs0, c4[2] - mu0 * dqs[ehi], cqs[ehi])));
            qT[(l0 + 1) * 68 + ehi] = tf32f(phi_fn(fmaf(rs1, c4[3] - mu1 * dqs[ehi], cqs[ehi])));
        }
    }
    // restage wA <- WoA (Wq reads done at the pre-scatter sync)
#pragma unroll
    for (int i = 0; i < 4; i++) {
        int idx = tid + i * 256;
        int e = idx >> 4, c = (idx & 15) * 4;
        *(float4*)(wA + e * 68 + c) = ((const float4*)g_WoA)[idx];
    }
    __syncthreads();

    // ---- attention: each thread owns half a qT row (4 heads), in place ----
    {
        int la = tid & 127, hgrp = tid >> 7;
        float* row = qT + la * 68 + hgrp * 32;
#pragma unroll
        for (int t = 0; t < 4; t++) {
            int hh = hgrp * 4 + t;
            float4 q0 = *(const float4*)(row + t * 8);
            float4 q1 = *(const float4*)(row + t * 8 + 4);
            float q[8] = {q0.x, q0.y, q0.z, q0.w, q1.x, q1.y, q1.z, q1.w};
            float nrm = 1e-6f;
#pragma unroll
            for (int d = 0; d < 8; d++) nrm = fmaf(q[d], Zs[hh * 8 + d], nrm);
            float inv = 1.f / nrm;
            float s[8] = {0.f, 0.f, 0.f, 0.f, 0.f, 0.f, 0.f, 0.f};
#pragma unroll
            for (int d = 0; d < 8; d++) {
                float4 kv0 = *(const float4*)(KVs + hh * 64 + d * 8);
                float4 kv1 = *(const float4*)(KVs + hh * 64 + d * 8 + 4);
                float qd = q[d];
                s[0] = fmaf(qd, kv0.x, s[0]); s[1] = fmaf(qd, kv0.y, s[1]);
                s[2] = fmaf(qd, kv0.z, s[2]); s[3] = fmaf(qd, kv0.w, s[3]);
                s[4] = fmaf(qd, kv1.x, s[4]); s[5] = fmaf(qd, kv1.y, s[5]);
                s[6] = fmaf(qd, kv1.z, s[6]); s[7] = fmaf(qd, kv1.w, s[7]);
            }
            *(float4*)(row + t * 8) = make_float4(
                tf32f(s[0] * inv), tf32f(s[1] * inv), tf32f(s[2] * inv), tf32f(s[3] * inv));
            *(float4*)(row + t * 8 + 4) = make_float4(
                tf32f(s[4] * inv), tf32f(s[5] * inv), tf32f(s[6] * inv), tf32f(s[7] * inv));
        }
    }
    __syncthreads();

    // ---- Wo GEMM via mma (A=WoA, B=attT=qT) ----
    float aO[2][4][4];
#pragma unroll
    for (int mi = 0; mi < 2; mi++)
#pragma unroll
        for (int ni = 0; ni < 4; ni++)
#pragma unroll
            for (int q = 0; q < 4; q++) aO[mi][ni][q] = 0.f;
#pragma unroll
    for (int kt = 0; kt < 8; kt++) {
        unsigned Ao[2][4], Bf[4][2];
#pragma unroll
        for (int mi = 0; mi < 2; mi++) {
            const float* ao = wA + (mtg * 32 + mi * 16 + gid) * 68 + kt * 8 + tig;
            Ao[mi][0] = __float_as_uint(ao[0]);
            Ao[mi][1] = __float_as_uint(ao[8 * 68]);
            Ao[mi][2] = __float_as_uint(ao[4]);
            Ao[mi][3] = __float_as_uint(ao[8 * 68 + 4]);
        }
#pragma unroll
        for (int ni = 0; ni < 4; ni++) {
            const float* bb = qT + (ntg * 32 + ni * 8 + gid) * 68 + kt * 8 + tig;
            Bf[ni][0] = __float_as_uint(bb[0]);
            Bf[ni][1] = __float_as_uint(bb[4]);
        }
#pragma unroll
        for (int mi = 0; mi < 2; mi++)
#pragma unroll
            for (int ni = 0; ni < 4; ni++)
                mma_tf32(aO[mi][ni], Ao[mi], Bf[ni]);
    }
    __syncthreads();   // all attT/wA reads done before Wlin slab overwrites them

    // ---- epilogue: y = c + bo + residual(x) -> tf32 -> buf1; stage Wlin slab ----
    float* yb = xfl;
#pragma unroll
    for (int mi = 0; mi < 2; mi++) {
        int fl = mtg * 32 + mi * 16 + gid, fh = fl + 8;
        float bbl = bos[fl], bbh = bos[fh];
        float al = As[fl], cl = Cs[fl], ah = As[fh], ch = Cs[fh];
        const float* xl = x + ((size_t)(b * 64 + fl)) * Ln + l0b;
        const float* xh = x + ((size_t)(b * 64 + fh)) * Ln + l0b;
#pragma unroll
        for (int ni = 0; ni < 4; ni++) {
            int l0 = ntg * 32 + ni * 8 + 2 * tig;
            float2 rl = *(const float2*)(xl + l0);
            float2 rh = *(const float2*)(xh + l0);
            float* c4 = aO[mi][ni];
            *(ull*)(yb + fl * 132 + l0) = pk2(
                tf32f(c4[0] + bbl + fmaf(rl.x, al, cl)),
                tf32f(c4[1] + bbl + fmaf(rl.y, al, cl)));
            *(ull*)(yb + fh * 132 + l0) = pk2(
                tf32f(c4[2] + bbh + fmaf(rh.x, ah, ch)),
                tf32f(c4[3] + bbh + fmaf(rh.y, ah, ch)));
        }
    }
#pragma unroll
    for (int i = 0; i < 12; i++) {
        int idx = tid + i * 256;               // 3072 float4 = 96 rows x 32
        int p = idx >> 5, c4 = idx & 31;
        float4 v = *(const float4*)(Wlin + (size_t)p * Ln + l0b + c4 * 4);
        v.x = tf32f(v.x); v.y = tf32f(v.y); v.z = tf32f(v.z); v.w = tf32f(v.w);
        *(float4*)(wls + p * 132 + c4 * 4) = v;
    }
    __syncthreads();

    // ---- temporal GEMM via mma (A=Wlin s132, B=y s132) ----
    {
        int mtg2 = w & 1, ntg2 = w >> 1;
        float c[3][2][4];
#pragma unroll
        for (int mi = 0; mi < 3; mi++)
#pragma unroll
            for (int ni = 0; ni < 2; ni++)
#pragma unroll
                for (int q = 0; q < 4; q++) c[mi][ni][q] = 0.f;
#pragma unroll
        for (int kt = 0; kt < 16; kt++) {
            int lcol = kt * 8 + tig;
            unsigned a[3][4], bf[2][2];
#pragma unroll
            for (int mi = 0; mi < 3; mi++) {
                const float* ab = wls + (mtg2 * 48 + mi * 16 + gid) * 132 + lcol;
                a[mi][0] = __float_as_uint(ab[0]);
                a[mi][1] = __float_as_uint(ab[8 * 132]);
                a[mi][2] = __float_as_uint(ab[4]);
                a[mi][3] = __float_as_uint(ab[8 * 132 + 4]);
            }
#pragma unroll
            for (int ni = 0; ni < 2; ni++) {
                const float* bb = yb + (ntg2 * 16 + ni * 8 + gid) * 132 + lcol;
                bf[ni][0] = __float_as_uint(bb[0]);
                bf[ni][1] = __float_as_uint(bb[4]);
            }
#pragma unroll
            for (int mi = 0; mi < 3; mi++)
#pragma unroll
                for (int ni = 0; ni < 2; ni++)
                    mma_tf32(c[mi][ni], a[mi], bf[ni]);
        }
#pragma unroll
        for (int mi = 0; mi < 3; mi++) {
            int p0 = mtg2 * 48 + mi * 16 + gid;
#pragma unroll
            for (int ni = 0; ni < 2; ni++) {
                int f0 = ntg2 * 16 + ni * 8 + 2 * tig;
                float* mb = &g_M[(b * 96 + p0) * 64 + f0];
                atomicAdd(mb,              c[mi][ni][0]);
                atomicAdd(mb + 1,          c[mi][ni][1]);
                atomicAdd(mb + 8 * 64,     c[mi][ni][2]);
                atomicAdd(mb + 8 * 64 + 1, c[mi][ni][3]);
            }
        }
    }
}

// ---------------- kernel 5: denorm + projector ----------------
__global__ void k_epi(const float* __restrict__ gamma, const float* __restrict__ beta,
                      const float* __restrict__ blin, const float* __restrict__ Wp,
                      const float* __restrict__ bp, float* __restrict__ out) {
    int b = blockIdx.x, p = threadIdx.x;
    float bl = blin[p];
    float s = bp[0];
#pragma unroll
    for (int f = 0; f < 64; f++) {
        float y = g_M[(b * 96 + p) * 64 + f] + bl;
        y = (y - beta[f]) / gamma[f];
        y = fmaf(y, g_stdp[b * 64 + f], g_mean[b * 64 + f]);
        s = fmaf(y, Wp[f], s);
    }
    out[b * 96 + p] = s;
}

// ---------------- launch ----------------
extern "C" void kernel_launch(void* const* d_in, const int* in_sizes, int n_in,
                              void* d_out, int out_size) {
    (void)in_sizes; (void)n_in; (void)out_size;
    const float* x     = (const float*)d_in[0];
    const float* gamma = (const float*)d_in[1];
    const float* beta  = (const float*)d_in[2];
    const float* lnw   = (const float*)d_in[3];
    const float* lnb   = (const float*)d_in[4];
    const float* Wq    = (const float*)d_in[5];
    const float* bq    = (const float*)d_in[6];
    const float* Wk    = (const float*)d_in[7];
    const float* bk    = (const float*)d_in[8];
    const float* Wv    = (const float*)d_in[9];
    const float* bv    = (const float*)d_in[10];
    const float* Wo    = (const float*)d_in[11];
    const float* bo    = (const float*)d_in[12];
    const float* Wlin  = (const float*)d_in[13];
    const float* blin  = (const float*)d_in[14];
    const float* Wp    = (const float*)d_in[15];
    const float* bp    = (const float*)d_in[16];
    float* out = (float*)d_out;

    const int SMB_KV = (8448 + 8704 + 2 * 4352) * 4;   // 103424 B
    const int SMB_QO = (8448 + 8704 + 4352) * 4;       // 86016 B
    cudaFuncSetAttribute(k_kv, cudaFuncAttributeMaxDynamicSharedMemorySize, SMB_KV);
    cudaFuncSetAttribute(k_qo, cudaFuncAttributeMaxDynamicSharedMemorySize, SMB_QO);

    k_prep<<<33, 256>>>(lnw, lnb, Wq, bq, Wk, bk, Wv, bv, Wo);
    k_stats<<<Bn * Fn, 256>>>(x);
    k_kv<<<dim3(Ln / 128, Bn), 256, SMB_KV>>>(x, gamma, beta);
    k_qo<<<dim3(Ln / 128, Bn), 256, SMB_QO>>>(x, gamma, beta, bo, Wlin);
    k_epi<<<Bn, Pn>>>(gamma, beta, blin, Wp, bp, out);
}